// round 3
// baseline (speedup 1.0000x reference)
#include <cuda_runtime.h>
#include <cstdint>

// ---------------------------------------------------------------------------
// Problem dims
// ---------------------------------------------------------------------------
#define Bdim 4
#define Tdim 2048
#define Cdim 1024
#define Hdim 16
#define Rdim 256
#define Sdim 64
#define Ddim 64
#define Mrows (Bdim * Tdim)   // 8192
#define ATTN_SCALE 0.125f     // 1/sqrt(64)

// Scratch (no allocation allowed -> device globals)
__device__ float g_latent[Mrows * Rdim];                 //  8 MB
__device__ float g_q[Bdim * Hdim * Tdim * Sdim];         // 32 MB
__device__ float g_k[Bdim * Hdim * Tdim * Sdim];         // 32 MB
__device__ float g_v[Bdim * Hdim * Tdim * Ddim];         // 32 MB  [B,H,T,D]
__device__ float g_y[Mrows * Cdim];                      // 32 MB
__device__ float g_w[Hdim * 128 * 256];                  //  2 MB  [H][128][256] = [Uh^T ; Vh^T]

// ---------------------------------------------------------------------------
// tf32 helpers (mma.sync path — works on compute_103 virtual arch)
// ---------------------------------------------------------------------------
__device__ __forceinline__ float to_tf32(float x) {
    uint32_t r;
    asm("cvt.rna.tf32.f32 %0, %1;" : "=r"(r) : "f"(x));
    return __uint_as_float(r);
}

__device__ __forceinline__ void mma_tf32(float& d0, float& d1, float& d2, float& d3,
                                         uint32_t a0, uint32_t a1, uint32_t a2, uint32_t a3,
                                         uint32_t b0, uint32_t b1)
{
    asm volatile(
        "mma.sync.aligned.m16n8k8.row.col.f32.tf32.tf32.f32 "
        "{%0,%1,%2,%3}, {%4,%5,%6,%7}, {%8,%9}, {%0,%1,%2,%3};"
        : "+f"(d0), "+f"(d1), "+f"(d2), "+f"(d3)
        : "r"(a0), "r"(a1), "r"(a2), "r"(a3), "r"(b0), "r"(b1));
}

// ---------------------------------------------------------------------------
// Build concatenated transposed factor weights:
// g_w[h][n][r] = u_factor[h][r][n]   n in [0,64)
//             = v_factor[h][r][n-64] n in [64,128)
// ---------------------------------------------------------------------------
__global__ void build_w(const float* __restrict__ u, const float* __restrict__ v,
                        float* __restrict__ w)
{
    int idx = blockIdx.x * 256 + threadIdx.x;
    if (idx >= Hdim * 128 * 256) return;
    int r = idx & 255;
    int n = (idx >> 8) & 127;
    int h = idx >> 15;
    float val = (n < 64)
        ? u[((size_t)h * Rdim + r) * Sdim + n]
        : v[((size_t)h * Rdim + r) * Sdim + (n - 64)];
    w[idx] = val;
}

// ---------------------------------------------------------------------------
// mma.sync tf32 NT GEMM: C[M,N] = A[M,K] * B[N,K]^T (+bias)
// CTA tile 128x128, BK=32, 8 warps (2 x 4), warp tile 64x32.
// LAYOUT 0: row-major [M,Ndim_]
// LAYOUT 1: remap to V layout [B,H,T,D]
// LAYOUT 2: q/k split (cols 0..63 -> C, 64..127 -> C2), head = blockIdx.z
// ---------------------------------------------------------------------------
#define LDS_PAD 36
template <int LAYOUT, bool HAS_BIAS>
__global__ void __launch_bounds__(256)
gemm_mma(const float* __restrict__ A, const float* __restrict__ Bw,
         const float* __restrict__ bias, float* __restrict__ C,
         float* __restrict__ C2, int Ndim_, int Kdim_)
{
    extern __shared__ float smem[];
    float* As = smem;                       // [2][128][36]
    float* Bs = smem + 2 * 128 * LDS_PAD;   // [2][128][36]

    const int tid = threadIdx.x;
    const int lane = tid & 31;
    const int warp = tid >> 5;
    const int wy = warp & 1;      // 0..1 along M (64 each)
    const int wx = warp >> 1;     // 0..3 along N (32 each)

    const int bm = blockIdx.y * 128;
    const int bn = blockIdx.x * 128;
    if (LAYOUT == 2) Bw += (size_t)blockIdx.z * (128 * 256);

    // staging mapping: thread covers rows sr, sr+32, sr+64, sr+96 at cols sc..sc+3
    const int sr = tid >> 3;
    const int sc = (tid & 7) * 4;

    float4 pa[4], pb[4];
    const float* Abase = A + (size_t)bm * Kdim_;
    const float* Bbase = Bw + (size_t)bn * Kdim_;

    float acc[4][4][4];
#pragma unroll
    for (int i = 0; i < 4; i++)
#pragma unroll
        for (int j = 0; j < 4; j++)
#pragma unroll
            for (int e = 0; e < 4; e++) acc[i][j][e] = 0.f;

    const int nch = Kdim_ >> 5;

    // prologue: load + store chunk 0
#pragma unroll
    for (int i = 0; i < 4; i++) {
        pa[i] = *(const float4*)(Abase + (size_t)(sr + i * 32) * Kdim_ + sc);
        pb[i] = *(const float4*)(Bbase + (size_t)(sr + i * 32) * Kdim_ + sc);
    }
#pragma unroll
    for (int i = 0; i < 4; i++) {
        float* ad = As + (sr + i * 32) * LDS_PAD + sc;
        float* bd = Bs + (sr + i * 32) * LDS_PAD + sc;
        ad[0] = to_tf32(pa[i].x); ad[1] = to_tf32(pa[i].y);
        ad[2] = to_tf32(pa[i].z); ad[3] = to_tf32(pa[i].w);
        bd[0] = to_tf32(pb[i].x); bd[1] = to_tf32(pb[i].y);
        bd[2] = to_tf32(pb[i].z); bd[3] = to_tf32(pb[i].w);
    }
    __syncthreads();

    for (int ch = 0; ch < nch; ch++) {
        const int buf = ch & 1;
        // prefetch next chunk into registers
        if (ch + 1 < nch) {
            const float* An = Abase + (ch + 1) * 32;
            const float* Bn = Bbase + (ch + 1) * 32;
#pragma unroll
            for (int i = 0; i < 4; i++) {
                pa[i] = *(const float4*)(An + (size_t)(sr + i * 32) * Kdim_ + sc);
                pb[i] = *(const float4*)(Bn + (size_t)(sr + i * 32) * Kdim_ + sc);
            }
        }

        // compute on buf
        {
            const float* Ab = As + buf * 128 * LDS_PAD + (wy * 64) * LDS_PAD;
            const float* Bb = Bs + buf * 128 * LDS_PAD + (wx * 32) * LDS_PAD;
            const int g = lane >> 2;      // groupID
            const int tg = lane & 3;      // thread in group
#pragma unroll
            for (int ks = 0; ks < 4; ks++) {
                const int k0 = ks * 8;
                uint32_t af[4][4];
#pragma unroll
                for (int mf = 0; mf < 4; mf++) {
                    const float* ap = Ab + (mf * 16 + g) * LDS_PAD + k0 + tg;
                    af[mf][0] = __float_as_uint(ap[0]);
                    af[mf][1] = __float_as_uint(ap[8 * LDS_PAD]);
                    af[mf][2] = __float_as_uint(ap[4]);
                    af[mf][3] = __float_as_uint(ap[8 * LDS_PAD + 4]);
                }
                uint32_t bf[4][2];
#pragma unroll
                for (int nf = 0; nf < 4; nf++) {
                    const float* bp = Bb + (nf * 8 + g) * LDS_PAD + k0 + tg;
                    bf[nf][0] = __float_as_uint(bp[0]);
                    bf[nf][1] = __float_as_uint(bp[4]);
                }
#pragma unroll
                for (int mf = 0; mf < 4; mf++)
#pragma unroll
                    for (int nf = 0; nf < 4; nf++)
                        mma_tf32(acc[mf][nf][0], acc[mf][nf][1], acc[mf][nf][2], acc[mf][nf][3],
                                 af[mf][0], af[mf][1], af[mf][2], af[mf][3],
                                 bf[nf][0], bf[nf][1]);
            }
        }

        // store prefetched chunk into the other buffer
        if (ch + 1 < nch) {
            const int nb = (ch + 1) & 1;
            float* Ad = As + nb * 128 * LDS_PAD;
            float* Bd = Bs + nb * 128 * LDS_PAD;
#pragma unroll
            for (int i = 0; i < 4; i++) {
                float* ad = Ad + (sr + i * 32) * LDS_PAD + sc;
                float* bd = Bd + (sr + i * 32) * LDS_PAD + sc;
                ad[0] = to_tf32(pa[i].x); ad[1] = to_tf32(pa[i].y);
                ad[2] = to_tf32(pa[i].z); ad[3] = to_tf32(pa[i].w);
                bd[0] = to_tf32(pb[i].x); bd[1] = to_tf32(pb[i].y);
                bd[2] = to_tf32(pb[i].z); bd[3] = to_tf32(pb[i].w);
            }
            __syncthreads();
        }
    }

    // ------------------------------------------------------------------ epilogue
    const int g = lane >> 2;
    const int tg = lane & 3;
#pragma unroll
    for (int mf = 0; mf < 4; mf++) {
#pragma unroll
        for (int nf = 0; nf < 4; nf++) {
            const int m0 = bm + wy * 64 + mf * 16 + g;
            const int n0 = bn + wx * 32 + nf * 8 + tg * 2;
            float b0 = 0.f, b1 = 0.f;
            if (HAS_BIAS) { b0 = bias[n0]; b1 = bias[n0 + 1]; }
            float2 lo = make_float2(acc[mf][nf][0] + b0, acc[mf][nf][1] + b1);
            float2 hi = make_float2(acc[mf][nf][2] + b0, acc[mf][nf][3] + b1);

            if (LAYOUT == 0) {
                *(float2*)(C + (size_t)m0 * Ndim_ + n0) = lo;
                *(float2*)(C + (size_t)(m0 + 8) * Ndim_ + n0) = hi;
            } else if (LAYOUT == 1) {
                const int h = n0 >> 6, d = n0 & 63;
                const int b_ = m0 >> 11, t = m0 & 2047;
                float* dst = C + (((size_t)b_ * Hdim + h) * Tdim + t) * Ddim + d;
                *(float2*)dst = lo;
                *(float2*)(dst + 8 * Ddim) = hi;   // m0+8: same b,h; t+8
            } else {  // LAYOUT 2
                const int h = blockIdx.z;
                float* base = (n0 < 64) ? C : C2;
                const int s0 = n0 & 63;
                const int b_ = m0 >> 11, t = m0 & 2047;
                float* dst = base + (((size_t)b_ * Hdim + h) * Tdim + t) * Sdim + s0;
                *(float2*)dst = lo;
                *(float2*)(dst + 8 * Sdim) = hi;
            }
        }
    }
}

// ---------------------------------------------------------------------------
// Causal flash attention, fp32.  64x64 tiles, online softmax. (unchanged)
// ---------------------------------------------------------------------------
__global__ void __launch_bounds__(256)
flash_attn(const float* __restrict__ q, const float* __restrict__ k,
           const float* __restrict__ v, float* __restrict__ y)
{
    __shared__ float Qst[64 * 64];
    __shared__ float KPs[64 * 64];
    __shared__ float Vs[64 * 64];

    const int bh = blockIdx.y;
    const int b = bh / Hdim, h = bh % Hdim;
    const int q0 = blockIdx.x * 64;
    const float* Q = q + (size_t)bh * Tdim * Sdim;
    const float* K = k + (size_t)bh * Tdim * Sdim;
    const float* V = v + (size_t)bh * Tdim * Ddim;

    const int tid = threadIdx.x;
    const int tx = tid & 15;
    const int ty = tid >> 4;

#pragma unroll
    for (int i = 0; i < 4; i++) {
        int f = tid + i * 256;
        int r = f >> 4, c4 = f & 15;
        float4 v4 = *(const float4*)&Q[(size_t)(q0 + r) * Sdim + c4 * 4];
        Qst[(c4 * 4 + 0) * 64 + r] = v4.x;
        Qst[(c4 * 4 + 1) * 64 + r] = v4.y;
        Qst[(c4 * 4 + 2) * 64 + r] = v4.z;
        Qst[(c4 * 4 + 3) * 64 + r] = v4.w;
    }

    float o[4][4];
    float mrow[4], lrow[4];
#pragma unroll
    for (int i = 0; i < 4; i++) {
        mrow[i] = -1e30f; lrow[i] = 0.f;
#pragma unroll
        for (int j = 0; j < 4; j++) o[i][j] = 0.f;
    }
    __syncthreads();

    const int nkt = blockIdx.x + 1;
    for (int kt = 0; kt < nkt; kt++) {
        const int k0 = kt * 64;
#pragma unroll
        for (int i = 0; i < 4; i++) {
            int f = tid + i * 256;
            int r = f >> 4, c4 = f & 15;
            float4 kv = *(const float4*)&K[(size_t)(k0 + r) * Sdim + c4 * 4];
            KPs[(c4 * 4 + 0) * 64 + r] = kv.x;
            KPs[(c4 * 4 + 1) * 64 + r] = kv.y;
            KPs[(c4 * 4 + 2) * 64 + r] = kv.z;
            KPs[(c4 * 4 + 3) * 64 + r] = kv.w;
            *(float4*)&Vs[r * 64 + c4 * 4] = *(const float4*)&V[(size_t)(k0 + r) * Ddim + c4 * 4];
        }
        __syncthreads();

        float s[4][4];
#pragma unroll
        for (int i = 0; i < 4; i++)
#pragma unroll
            for (int j = 0; j < 4; j++) s[i][j] = 0.f;
#pragma unroll
        for (int kk = 0; kk < 64; kk++) {
            float qa[4], kb[4];
#pragma unroll
            for (int i = 0; i < 4; i++) qa[i] = Qst[kk * 64 + ty * 4 + i];
#pragma unroll
            for (int j = 0; j < 4; j++) kb[j] = KPs[kk * 64 + tx * 4 + j];
#pragma unroll
            for (int i = 0; i < 4; i++)
#pragma unroll
                for (int j = 0; j < 4; j++)
                    s[i][j] = fmaf(qa[i], kb[j], s[i][j]);
        }
        __syncthreads();

        const bool diag = (kt == blockIdx.x);
#pragma unroll
        for (int i = 0; i < 4; i++)
#pragma unroll
            for (int j = 0; j < 4; j++) {
                s[i][j] *= ATTN_SCALE;
                if (diag && (k0 + tx * 4 + j) > (q0 + ty * 4 + i)) s[i][j] = -1e30f;
            }

#pragma unroll
        for (int i = 0; i < 4; i++) {
            float mx = fmaxf(fmaxf(s[i][0], s[i][1]), fmaxf(s[i][2], s[i][3]));
#pragma unroll
            for (int off = 8; off >= 1; off >>= 1)
                mx = fmaxf(mx, __shfl_xor_sync(0xffffffffu, mx, off));
            float mnew = fmaxf(mrow[i], mx);
            float alpha = __expf(mrow[i] - mnew);
            mrow[i] = mnew;
            float rs = 0.f;
#pragma unroll
            for (int j = 0; j < 4; j++) { s[i][j] = __expf(s[i][j] - mnew); rs += s[i][j]; }
#pragma unroll
            for (int off = 8; off >= 1; off >>= 1)
                rs += __shfl_xor_sync(0xffffffffu, rs, off);
            lrow[i] = lrow[i] * alpha + rs;
#pragma unroll
            for (int j = 0; j < 4; j++) o[i][j] *= alpha;
        }

#pragma unroll
        for (int i = 0; i < 4; i++)
            *(float4*)&KPs[(ty * 4 + i) * 64 + tx * 4] =
                make_float4(s[i][0], s[i][1], s[i][2], s[i][3]);
        __syncthreads();

#pragma unroll
        for (int kk = 0; kk < 64; kk++) {
            float pv[4], vv[4];
#pragma unroll
            for (int i = 0; i < 4; i++) pv[i] = KPs[(ty * 4 + i) * 64 + kk];
#pragma unroll
            for (int j = 0; j < 4; j++) vv[j] = Vs[kk * 64 + tx * 4 + j];
#pragma unroll
            for (int i = 0; i < 4; i++)
#pragma unroll
                for (int j = 0; j < 4; j++)
                    o[i][j] = fmaf(pv[i], vv[j], o[i][j]);
        }
        __syncthreads();
    }

#pragma unroll
    for (int i = 0; i < 4; i++) {
        float inv = 1.f / lrow[i];
        int t = q0 + ty * 4 + i;
        size_t base = ((size_t)b * Tdim + t) * Cdim + h * Ddim + tx * 4;
        *(float4*)&y[base] =
            make_float4(o[i][0] * inv, o[i][1] * inv, o[i][2] * inv, o[i][3] * inv);
    }
}

// ---------------------------------------------------------------------------
extern "C" void kernel_launch(void* const* d_in, const int* in_sizes, int n_in,
                              void* d_out, int out_size)
{
    const float* x  = (const float*)d_in[0];   // hidden_states [B,T,C]
    const float* bw = (const float*)d_in[1];   // basis_w [R,C]
    const float* uf = (const float*)d_in[2];   // u_factor [H,R,S]
    const float* vf = (const float*)d_in[3];   // v_factor [H,R,S]
    const float* vw = (const float*)d_in[4];   // v_proj_w [C,C]
    const float* vb = (const float*)d_in[5];   // v_proj_b [C]
    const float* ow = (const float*)d_in[6];   // o_proj_w [C,C]
    const float* ob = (const float*)d_in[7];   // o_proj_b [C]
    float* out = (float*)d_out;

    float *latent, *q, *k, *v, *y, *w;
    cudaGetSymbolAddress((void**)&latent, g_latent);
    cudaGetSymbolAddress((void**)&q, g_q);
    cudaGetSymbolAddress((void**)&k, g_k);
    cudaGetSymbolAddress((void**)&v, g_v);
    cudaGetSymbolAddress((void**)&y, g_y);
    cudaGetSymbolAddress((void**)&w, g_w);

    const int SMEM = 2 * 2 * 128 * LDS_PAD * 4;   // 73728 bytes
    cudaFuncSetAttribute(gemm_mma<0, false>, cudaFuncAttributeMaxDynamicSharedMemorySize, SMEM);
    cudaFuncSetAttribute(gemm_mma<0, true >, cudaFuncAttributeMaxDynamicSharedMemorySize, SMEM);
    cudaFuncSetAttribute(gemm_mma<1, true >, cudaFuncAttributeMaxDynamicSharedMemorySize, SMEM);
    cudaFuncSetAttribute(gemm_mma<2, false>, cudaFuncAttributeMaxDynamicSharedMemorySize, SMEM);

    // Build transposed factor weights [H,128,256]
    build_w<<<(Hdim * 128 * 256 + 255) / 256, 256>>>(uf, vf, w);

    // latent = x * basis_w^T            [8192,256], K=1024
    gemm_mma<0, false><<<dim3(Rdim / 128, Mrows / 128), 256, SMEM>>>(
        x, bw, nullptr, latent, nullptr, Rdim, Cdim);

    // q,k = latent * [Uh^T;Vh^T]^T      per head, K=256
    gemm_mma<2, false><<<dim3(1, Mrows / 128, Hdim), 256, SMEM>>>(
        latent, w, nullptr, q, k, 128, Rdim);

    // v = x * v_proj_w^T + b   -> [B,H,T,D], K=1024
    gemm_mma<1, true><<<dim3(Cdim / 128, Mrows / 128), 256, SMEM>>>(
        x, vw, vb, v, nullptr, Cdim, Cdim);

    // causal flash attention -> y [B,T,C]
    flash_attn<<<dim3(Tdim / 64, Bdim * Hdim), 256>>>(q, k, v, y);

    // out = y * o_proj_w^T + b, K=1024
    gemm_mma<0, true><<<dim3(Cdim / 128, Mrows / 128), 256, SMEM>>>(
        y, ow, ob, out, nullptr, Cdim, Cdim);
}

// round 4
// speedup vs baseline: 3.3331x; 3.3331x over previous
#include <cuda_runtime.h>
#include <cstdint>

// ---------------------------------------------------------------------------
// Problem dims
// ---------------------------------------------------------------------------
#define Bdim 4
#define Tdim 2048
#define Cdim 1024
#define Hdim 16
#define Rdim 256
#define Sdim 64
#define Ddim 64
#define Mrows (Bdim * Tdim)   // 8192
#define ATTN_SCALE 0.125f     // 1/sqrt(64)

// Scratch (device globals; no allocation allowed)
__device__ float g_latent[Mrows * Rdim];
__device__ float g_q[Bdim * Hdim * Tdim * Sdim];
__device__ float g_k[Bdim * Hdim * Tdim * Sdim];
__device__ float g_v[Bdim * Hdim * Tdim * Ddim];
__device__ float g_y[Mrows * Cdim];
__device__ float g_w[Hdim * 128 * 256];      // [H][128][256] = [Uh^T ; Vh^T], tf32
__device__ float g_xt[Mrows * Cdim];         // x rounded to tf32
__device__ float g_bwt[Rdim * Cdim];         // basis_w tf32
__device__ float g_vwt[Cdim * Cdim];         // v_proj_w tf32
__device__ float g_owt[Cdim * Cdim];         // o_proj_w tf32

// ---------------------------------------------------------------------------
// helpers
// ---------------------------------------------------------------------------
__device__ __forceinline__ float to_tf32(float x) {
    uint32_t r;
    asm("cvt.rna.tf32.f32 %0, %1;" : "=r"(r) : "f"(x));
    return __uint_as_float(r);
}

__device__ __forceinline__ void mma_tf32(float& d0, float& d1, float& d2, float& d3,
                                         uint32_t a0, uint32_t a1, uint32_t a2, uint32_t a3,
                                         uint32_t b0, uint32_t b1)
{
    asm volatile(
        "mma.sync.aligned.m16n8k8.row.col.f32.tf32.tf32.f32 "
        "{%0,%1,%2,%3}, {%4,%5,%6,%7}, {%8,%9}, {%0,%1,%2,%3};"
        : "+f"(d0), "+f"(d1), "+f"(d2), "+f"(d3)
        : "r"(a0), "r"(a1), "r"(a2), "r"(a3), "r"(b0), "r"(b1));
}

__device__ __forceinline__ void cp16(void* dst_smem, const void* src) {
    uint32_t s = (uint32_t)__cvta_generic_to_shared(dst_smem);
    asm volatile("cp.async.ca.shared.global [%0], [%1], 16;" :: "r"(s), "l"(src));
}
#define CP_COMMIT() asm volatile("cp.async.commit_group;")
#define CP_WAIT0()  asm volatile("cp.async.wait_group 0;")
#define CP_WAIT1()  asm volatile("cp.async.wait_group 1;")

// FFMA-only exp (MUFU on B300 is rt=8/SMSP -> ~1ms for 134M exps; this is ~11 flops).
// Valid for x <= 0 (clamped at -87); exact enough for softmax (rel err ~2e-6).
__device__ __forceinline__ float fexp(float x) {
    x = fmaxf(x, -87.0f);
    float t = fmaf(x, 1.4426950408889634f, 12582912.f);   // round-to-int trick
    int   ib = __float_as_int(t);
    float i  = t - 12582912.f;
    float f  = fmaf(x, 1.4426950408889634f, -i);          // f in [-0.5, 0.5]
    float p  = fmaf(f, 0.00133336f, 0.0096181f);
    p = fmaf(f, p, 0.0555041f);
    p = fmaf(f, p, 0.2402265f);
    p = fmaf(f, p, 0.6931472f);
    p = fmaf(f, p, 1.0f);
    float sc = __int_as_float((ib << 23) + 0x3F800000);   // 2^i
    return sc * p;
}

// ---------------------------------------------------------------------------
// one-shot prep kernels
// ---------------------------------------------------------------------------
__global__ void cvt_tf32(const float* __restrict__ in, float* __restrict__ out, int n4) {
    int i = blockIdx.x * 256 + threadIdx.x;
    if (i >= n4) return;
    float4 v = ((const float4*)in)[i];
    v.x = to_tf32(v.x); v.y = to_tf32(v.y); v.z = to_tf32(v.z); v.w = to_tf32(v.w);
    ((float4*)out)[i] = v;
}

__global__ void build_w(const float* __restrict__ u, const float* __restrict__ v,
                        float* __restrict__ w)
{
    int idx = blockIdx.x * 256 + threadIdx.x;
    if (idx >= Hdim * 128 * 256) return;
    int r = idx & 255;
    int n = (idx >> 8) & 127;
    int h = idx >> 15;
    float val = (n < 64)
        ? u[((size_t)h * Rdim + r) * Sdim + n]
        : v[((size_t)h * Rdim + r) * Sdim + (n - 64)];
    w[idx] = to_tf32(val);
}

// ---------------------------------------------------------------------------
// mma.sync tf32 NT GEMM: C[M,N] = A[M,K] * B[N,K]^T (+bias)
// CTA 128x128, BK=32, 8 warps (2x4), warp tile 64x32. Inputs pre-rounded tf32.
// cp.async double-buffered staging.
// LAYOUT 0: row-major  LAYOUT 1: V remap [B,H,T,D]  LAYOUT 2: q/k split per head
// ---------------------------------------------------------------------------
#define LDS_PAD 36
template <int LAYOUT, bool HAS_BIAS, bool ROUND>
__global__ void __launch_bounds__(256, 2)
gemm_mma(const float* __restrict__ A, const float* __restrict__ Bw,
         const float* __restrict__ bias, float* __restrict__ C,
         float* __restrict__ C2, int Ndim_, int Kdim_)
{
    extern __shared__ float smem[];
    float* As = smem;                       // [2][128][36]
    float* Bs = smem + 2 * 128 * LDS_PAD;   // [2][128][36]

    const int tid = threadIdx.x;
    const int lane = tid & 31;
    const int warp = tid >> 5;
    const int wy = warp & 1;
    const int wx = warp >> 1;

    const int bm = blockIdx.y * 128;
    const int bn = blockIdx.x * 128;
    if (LAYOUT == 2) Bw += (size_t)blockIdx.z * (128 * 256);

    const int sr = tid >> 3;          // 0..31 (x4 rows)
    const int sc = (tid & 7) * 4;     // col offset

    const float* Abase = A + (size_t)bm * Kdim_;
    const float* Bbase = Bw + (size_t)bn * Kdim_;

    float acc[4][4][4];
#pragma unroll
    for (int i = 0; i < 4; i++)
#pragma unroll
        for (int j = 0; j < 4; j++)
#pragma unroll
            for (int e = 0; e < 4; e++) acc[i][j][e] = 0.f;

    const int nch = Kdim_ >> 5;

    auto load_chunk = [&](int ch, int buf) {
        const float* An = Abase + ch * 32;
        const float* Bn = Bbase + ch * 32;
        float* Ad = As + buf * 128 * LDS_PAD;
        float* Bd = Bs + buf * 128 * LDS_PAD;
#pragma unroll
        for (int i = 0; i < 4; i++) {
            int r = sr + i * 32;
            cp16(Ad + r * LDS_PAD + sc, An + (size_t)r * Kdim_ + sc);
            cp16(Bd + r * LDS_PAD + sc, Bn + (size_t)r * Kdim_ + sc);
        }
        CP_COMMIT();
    };

    load_chunk(0, 0);
    if (nch > 1) load_chunk(1, 1);

    const int g = lane >> 2;
    const int tg = lane & 3;

    for (int ch = 0; ch < nch; ch++) {
        if (ch + 1 < nch) { CP_WAIT1(); } else { CP_WAIT0(); }
        __syncthreads();

        const int buf = ch & 1;
        const float* Ab = As + buf * 128 * LDS_PAD + (wy * 64) * LDS_PAD;
        const float* Bb = Bs + buf * 128 * LDS_PAD + (wx * 32) * LDS_PAD;
#pragma unroll
        for (int ks = 0; ks < 4; ks++) {
            const int k0 = ks * 8;
            uint32_t af[4][4];
#pragma unroll
            for (int mf = 0; mf < 4; mf++) {
                const float* ap = Ab + (mf * 16 + g) * LDS_PAD + k0 + tg;
                af[mf][0] = __float_as_uint(ap[0]);
                af[mf][1] = __float_as_uint(ap[8 * LDS_PAD]);
                af[mf][2] = __float_as_uint(ap[4]);
                af[mf][3] = __float_as_uint(ap[8 * LDS_PAD + 4]);
            }
            uint32_t bf[4][2];
#pragma unroll
            for (int nf = 0; nf < 4; nf++) {
                const float* bp = Bb + (nf * 8 + g) * LDS_PAD + k0 + tg;
                bf[nf][0] = __float_as_uint(bp[0]);
                bf[nf][1] = __float_as_uint(bp[4]);
            }
#pragma unroll
            for (int mf = 0; mf < 4; mf++)
#pragma unroll
                for (int nf = 0; nf < 4; nf++)
                    mma_tf32(acc[mf][nf][0], acc[mf][nf][1], acc[mf][nf][2], acc[mf][nf][3],
                             af[mf][0], af[mf][1], af[mf][2], af[mf][3],
                             bf[nf][0], bf[nf][1]);
        }
        __syncthreads();
        if (ch + 2 < nch) load_chunk(ch + 2, buf);
    }

    // epilogue
#pragma unroll
    for (int mf = 0; mf < 4; mf++) {
#pragma unroll
        for (int nf = 0; nf < 4; nf++) {
            const int m0 = bm + wy * 64 + mf * 16 + g;
            const int n0 = bn + wx * 32 + nf * 8 + tg * 2;
            float v0 = acc[mf][nf][0], v1 = acc[mf][nf][1];
            float v2 = acc[mf][nf][2], v3 = acc[mf][nf][3];
            if (HAS_BIAS) {
                float b0 = bias[n0], b1 = bias[n0 + 1];
                v0 += b0; v1 += b1; v2 += b0; v3 += b1;
            }
            if (LAYOUT == 2 && n0 < 64) {   // q columns: fold attention scale
                v0 *= ATTN_SCALE; v1 *= ATTN_SCALE; v2 *= ATTN_SCALE; v3 *= ATTN_SCALE;
            }
            if (ROUND) {
                v0 = to_tf32(v0); v1 = to_tf32(v1); v2 = to_tf32(v2); v3 = to_tf32(v3);
            }
            float2 lo = make_float2(v0, v1);
            float2 hi = make_float2(v2, v3);

            if (LAYOUT == 0) {
                *(float2*)(C + (size_t)m0 * Ndim_ + n0) = lo;
                *(float2*)(C + (size_t)(m0 + 8) * Ndim_ + n0) = hi;
            } else if (LAYOUT == 1) {
                const int h = n0 >> 6, d = n0 & 63;
                const int b_ = m0 >> 11, t = m0 & 2047;
                float* dst = C + (((size_t)b_ * Hdim + h) * Tdim + t) * Ddim + d;
                *(float2*)dst = lo;
                *(float2*)(dst + 8 * Ddim) = hi;
            } else {
                const int h = blockIdx.z;
                float* base = (n0 < 64) ? C : C2;
                const int s0 = n0 & 63;
                const int b_ = m0 >> 11, t = m0 & 2047;
                float* dst = base + (((size_t)b_ * Hdim + h) * Tdim + t) * Sdim + s0;
                *(float2*)dst = lo;
                *(float2*)(dst + 8 * Sdim) = hi;
            }
        }
    }
}

// ---------------------------------------------------------------------------
// Flash attention on mma.sync tf32.
// Q tile 128 x 64, K/V tiles 64. 8 warps, warp owns 16 Q rows.
// q pre-scaled+tf32, k/v tf32. P via warp-private smem rows. fexp for softmax.
// ---------------------------------------------------------------------------
#define FPAD 68
__global__ void __launch_bounds__(256, 2)
flash_mma(const float* __restrict__ q, const float* __restrict__ k,
          const float* __restrict__ v, float* __restrict__ y)
{
    extern __shared__ float sm[];
    float* Qs = sm;                    // [128][68]
    float* Ks = Qs + 128 * FPAD;       // [64][68]
    float* Vt = Ks + 64 * FPAD;        // [64][68]  Vt[d][u]
    float* Ps = Vt + 64 * FPAD;        // [128][68]

    const int bh = blockIdx.y;
    const int b = bh >> 4, h = bh & 15;
    const int qb = (gridDim.x - 1) - blockIdx.x;   // heaviest tiles first
    const int q0 = qb * 128;
    const float* Q = q + (size_t)bh * Tdim * Sdim;
    const float* K = k + (size_t)bh * Tdim * Sdim;
    const float* V = v + (size_t)bh * Tdim * Ddim;

    const int tid = threadIdx.x;
    const int lane = tid & 31;
    const int warp = tid >> 5;
    const int wrow = warp * 16;
    const int g = lane >> 2;
    const int tg = lane & 3;

    // load Q tile (natural row-major): 128x16 float4 = 2048 -> 8/thread
#pragma unroll
    for (int i = 0; i < 8; i++) {
        int f = tid + i * 256;
        int r = f >> 4, c4 = f & 15;
        *(float4*)&Qs[r * FPAD + c4 * 4] = *(const float4*)&Q[(size_t)(q0 + r) * Sdim + c4 * 4];
    }

    float o[8][4];
#pragma unroll
    for (int df = 0; df < 8; df++)
#pragma unroll
        for (int e = 0; e < 4; e++) o[df][e] = 0.f;
    float m0 = -1e30f, m1 = -1e30f, l0 = 0.f, l1 = 0.f;

    __syncthreads();

    const int nkt = (q0 + 128) >> 6;
    for (int kt = 0; kt < nkt; kt++) {
        const int k0 = kt * 64;
        // load K natural + V transposed: 64x16 float4 = 1024 -> 4/thread
#pragma unroll
        for (int i = 0; i < 4; i++) {
            int f = tid + i * 256;
            int u = f >> 4, c4 = f & 15;
            *(float4*)&Ks[u * FPAD + c4 * 4] = *(const float4*)&K[(size_t)(k0 + u) * Sdim + c4 * 4];
            float4 v4 = *(const float4*)&V[(size_t)(k0 + u) * Ddim + c4 * 4];
            int d0 = c4 * 4;
            Vt[(d0 + 0) * FPAD + u] = v4.x;
            Vt[(d0 + 1) * FPAD + u] = v4.y;
            Vt[(d0 + 2) * FPAD + u] = v4.z;
            Vt[(d0 + 3) * FPAD + u] = v4.w;
        }
        __syncthreads();

        // S = Q K^T  (per warp: 16 x 64)
        float sacc[8][4];
#pragma unroll
        for (int jf = 0; jf < 8; jf++)
#pragma unroll
            for (int e = 0; e < 4; e++) sacc[jf][e] = 0.f;
#pragma unroll
        for (int ks = 0; ks < 8; ks++) {
            const int kk = ks * 8;
            const float* ap = Qs + (wrow + g) * FPAD + kk + tg;
            uint32_t a0 = __float_as_uint(ap[0]);
            uint32_t a1 = __float_as_uint(ap[8 * FPAD]);
            uint32_t a2 = __float_as_uint(ap[4]);
            uint32_t a3 = __float_as_uint(ap[8 * FPAD + 4]);
#pragma unroll
            for (int jf = 0; jf < 8; jf++) {
                const float* bp = Ks + (jf * 8 + g) * FPAD + kk + tg;
                mma_tf32(sacc[jf][0], sacc[jf][1], sacc[jf][2], sacc[jf][3],
                         a0, a1, a2, a3,
                         __float_as_uint(bp[0]), __float_as_uint(bp[4]));
            }
        }

        // causal mask (only tiles that cross this warp's rows)
        const int r0 = q0 + wrow + g;
        const int r1 = r0 + 8;
        if (k0 + 63 > q0 + wrow) {
#pragma unroll
            for (int jf = 0; jf < 8; jf++) {
                const int c0 = k0 + jf * 8 + 2 * tg;
                if (c0 > r0) sacc[jf][0] = -1e30f;
                if (c0 + 1 > r0) sacc[jf][1] = -1e30f;
                if (c0 > r1) sacc[jf][2] = -1e30f;
                if (c0 + 1 > r1) sacc[jf][3] = -1e30f;
            }
        }

        // online softmax (rows r0, r1; row shared by 4 lanes tg)
        float mx0 = -1e30f, mx1 = -1e30f;
#pragma unroll
        for (int jf = 0; jf < 8; jf++) {
            mx0 = fmaxf(mx0, fmaxf(sacc[jf][0], sacc[jf][1]));
            mx1 = fmaxf(mx1, fmaxf(sacc[jf][2], sacc[jf][3]));
        }
        mx0 = fmaxf(mx0, __shfl_xor_sync(0xffffffffu, mx0, 1));
        mx0 = fmaxf(mx0, __shfl_xor_sync(0xffffffffu, mx0, 2));
        mx1 = fmaxf(mx1, __shfl_xor_sync(0xffffffffu, mx1, 1));
        mx1 = fmaxf(mx1, __shfl_xor_sync(0xffffffffu, mx1, 2));

        float mn0 = fmaxf(m0, mx0), mn1 = fmaxf(m1, mx1);
        float al0 = fexp(m0 - mn0), al1 = fexp(m1 - mn1);
        m0 = mn0; m1 = mn1;

        float rs0 = 0.f, rs1 = 0.f;
#pragma unroll
        for (int jf = 0; jf < 8; jf++) {
            sacc[jf][0] = fexp(sacc[jf][0] - mn0);
            sacc[jf][1] = fexp(sacc[jf][1] - mn0);
            sacc[jf][2] = fexp(sacc[jf][2] - mn1);
            sacc[jf][3] = fexp(sacc[jf][3] - mn1);
            rs0 += sacc[jf][0] + sacc[jf][1];
            rs1 += sacc[jf][2] + sacc[jf][3];
        }
        rs0 += __shfl_xor_sync(0xffffffffu, rs0, 1);
        rs0 += __shfl_xor_sync(0xffffffffu, rs0, 2);
        rs1 += __shfl_xor_sync(0xffffffffu, rs1, 1);
        rs1 += __shfl_xor_sync(0xffffffffu, rs1, 2);
        l0 = l0 * al0 + rs0;
        l1 = l1 * al1 + rs1;

        // rescale O, stage P (tf32) into warp-private smem rows
#pragma unroll
        for (int df = 0; df < 8; df++) {
            o[df][0] *= al0; o[df][1] *= al0;
            o[df][2] *= al1; o[df][3] *= al1;
        }
#pragma unroll
        for (int jf = 0; jf < 8; jf++) {
            *(float2*)&Ps[(wrow + g) * FPAD + jf * 8 + 2 * tg] =
                make_float2(to_tf32(sacc[jf][0]), to_tf32(sacc[jf][1]));
            *(float2*)&Ps[(wrow + g + 8) * FPAD + jf * 8 + 2 * tg] =
                make_float2(to_tf32(sacc[jf][2]), to_tf32(sacc[jf][3]));
        }
        __syncwarp();

        // O += P V  (A = own 16 rows of Ps, B = Vt)
#pragma unroll
        for (int ks = 0; ks < 8; ks++) {
            const int kk = ks * 8;
            const float* ap = Ps + (wrow + g) * FPAD + kk + tg;
            uint32_t a0 = __float_as_uint(ap[0]);
            uint32_t a1 = __float_as_uint(ap[8 * FPAD]);
            uint32_t a2 = __float_as_uint(ap[4]);
            uint32_t a3 = __float_as_uint(ap[8 * FPAD + 4]);
#pragma unroll
            for (int df = 0; df < 8; df++) {
                const float* bp = Vt + (df * 8 + g) * FPAD + kk + tg;
                mma_tf32(o[df][0], o[df][1], o[df][2], o[df][3],
                         a0, a1, a2, a3,
                         __float_as_uint(bp[0]), __float_as_uint(bp[4]));
            }
        }
        __syncthreads();   // before next tile overwrites Ks/Vt
    }

    // epilogue: y[b, t, h*64 + d], tf32-rounded (feeds o-proj)
    const float inv0 = 1.f / l0, inv1 = 1.f / l1;
    const int r0 = q0 + wrow + g;
    float* y0 = y + ((size_t)b * Tdim + r0) * Cdim + h * 64;
    float* y1 = y + ((size_t)b * Tdim + r0 + 8) * Cdim + h * 64;
#pragma unroll
    for (int df = 0; df < 8; df++) {
        const int d0 = df * 8 + 2 * tg;
        *(float2*)(y0 + d0) = make_float2(to_tf32(o[df][0] * inv0), to_tf32(o[df][1] * inv0));
        *(float2*)(y1 + d0) = make_float2(to_tf32(o[df][2] * inv1), to_tf32(o[df][3] * inv1));
    }
}

// ---------------------------------------------------------------------------
extern "C" void kernel_launch(void* const* d_in, const int* in_sizes, int n_in,
                              void* d_out, int out_size)
{
    const float* x  = (const float*)d_in[0];
    const float* bw = (const float*)d_in[1];
    const float* uf = (const float*)d_in[2];
    const float* vf = (const float*)d_in[3];
    const float* vw = (const float*)d_in[4];
    const float* vb = (const float*)d_in[5];
    const float* ow = (const float*)d_in[6];
    const float* ob = (const float*)d_in[7];
    float* out = (float*)d_out;

    float *latent, *q, *k, *v, *y, *w, *xt, *bwt, *vwt, *owt;
    cudaGetSymbolAddress((void**)&latent, g_latent);
    cudaGetSymbolAddress((void**)&q, g_q);
    cudaGetSymbolAddress((void**)&k, g_k);
    cudaGetSymbolAddress((void**)&v, g_v);
    cudaGetSymbolAddress((void**)&y, g_y);
    cudaGetSymbolAddress((void**)&w, g_w);
    cudaGetSymbolAddress((void**)&xt, g_xt);
    cudaGetSymbolAddress((void**)&bwt, g_bwt);
    cudaGetSymbolAddress((void**)&vwt, g_vwt);
    cudaGetSymbolAddress((void**)&owt, g_owt);

    const int GSMEM = 2 * 2 * 128 * LDS_PAD * 4;           // 73728
    const int FSMEM = (128 + 64 + 64 + 128) * FPAD * 4;    // 104448
    cudaFuncSetAttribute(gemm_mma<0, false, true >, cudaFuncAttributeMaxDynamicSharedMemorySize, GSMEM);
    cudaFuncSetAttribute(gemm_mma<0, true,  false>, cudaFuncAttributeMaxDynamicSharedMemorySize, GSMEM);
    cudaFuncSetAttribute(gemm_mma<1, true,  true >, cudaFuncAttributeMaxDynamicSharedMemorySize, GSMEM);
    cudaFuncSetAttribute(gemm_mma<2, false, true >, cudaFuncAttributeMaxDynamicSharedMemorySize, GSMEM);
    cudaFuncSetAttribute(flash_mma, cudaFuncAttributeMaxDynamicSharedMemorySize, FSMEM);

    // one-shot tf32 pre-rounding
    cvt_tf32<<<(Mrows * Cdim / 4 + 255) / 256, 256>>>(x,  xt,  Mrows * Cdim / 4);
    cvt_tf32<<<(Rdim * Cdim / 4 + 255) / 256, 256>>>(bw, bwt, Rdim * Cdim / 4);
    cvt_tf32<<<(Cdim * Cdim / 4 + 255) / 256, 256>>>(vw, vwt, Cdim * Cdim / 4);
    cvt_tf32<<<(Cdim * Cdim / 4 + 255) / 256, 256>>>(ow, owt, Cdim * Cdim / 4);
    build_w<<<(Hdim * 128 * 256 + 255) / 256, 256>>>(uf, vf, w);

    // latent = x * basis_w^T  [8192,256] (tf32-rounded output)
    gemm_mma<0, false, true><<<dim3(Rdim / 128, Mrows / 128), 256, GSMEM>>>(
        xt, bwt, nullptr, latent, nullptr, Rdim, Cdim);

    // q,k per head (q pre-scaled; both tf32-rounded)
    gemm_mma<2, false, true><<<dim3(1, Mrows / 128, Hdim), 256, GSMEM>>>(
        latent, w, nullptr, q, k, 128, Rdim);

    // v = x * v_proj_w^T + b -> [B,H,T,D] (tf32-rounded)
    gemm_mma<1, true, true><<<dim3(Cdim / 128, Mrows / 128), 256, GSMEM>>>(
        xt, vwt, vb, v, nullptr, Cdim, Cdim);

    // causal flash attention (tensor cores) -> y [B,T,C] tf32-rounded
    flash_mma<<<dim3(Tdim / 128, Bdim * Hdim), 256, FSMEM>>>(q, k, v, y);

    // out = y * o_proj_w^T + b (full fp32 output)
    gemm_mma<0, true, false><<<dim3(Cdim / 128, Mrows / 128), 256, GSMEM>>>(
        y, owt, ob, out, nullptr, Cdim, Cdim);
}

// round 5
// speedup vs baseline: 3.6287x; 1.0887x over previous
#include <cuda_runtime.h>
#include <cstdint>

// ---------------------------------------------------------------------------
// Problem dims
// ---------------------------------------------------------------------------
#define Bdim 4
#define Tdim 2048
#define Cdim 1024
#define Hdim 16
#define Rdim 256
#define Sdim 64
#define Ddim 64
#define Mrows (Bdim * Tdim)   // 8192
#define ATTN_SCALE 0.125f     // 1/sqrt(64)

// Scratch (device globals; no allocation allowed)
__device__ float g_latent[Mrows * Rdim];
__device__ float g_q[Bdim * Hdim * Tdim * Sdim];
__device__ float g_k[Bdim * Hdim * Tdim * Sdim];
__device__ float g_v[Bdim * Hdim * Tdim * Ddim];
__device__ float g_y[Mrows * Cdim];
__device__ float g_w[Hdim * 128 * 256];      // [H][128][256] = [Uh^T ; Vh^T], tf32
__device__ float g_xt[Mrows * Cdim];         // x rounded to tf32
__device__ float g_bwt[Rdim * Cdim];         // basis_w tf32
__device__ float g_vwt[Cdim * Cdim];         // v_proj_w tf32
__device__ float g_owt[Cdim * Cdim];         // o_proj_w tf32

// ---------------------------------------------------------------------------
// helpers
// ---------------------------------------------------------------------------
__device__ __forceinline__ float to_tf32(float x) {
    uint32_t r;
    asm("cvt.rna.tf32.f32 %0, %1;" : "=r"(r) : "f"(x));
    return __uint_as_float(r);
}

__device__ __forceinline__ void mma_tf32(float& d0, float& d1, float& d2, float& d3,
                                         uint32_t a0, uint32_t a1, uint32_t a2, uint32_t a3,
                                         uint32_t b0, uint32_t b1)
{
    asm volatile(
        "mma.sync.aligned.m16n8k8.row.col.f32.tf32.tf32.f32 "
        "{%0,%1,%2,%3}, {%4,%5,%6,%7}, {%8,%9}, {%0,%1,%2,%3};"
        : "+f"(d0), "+f"(d1), "+f"(d2), "+f"(d3)
        : "r"(a0), "r"(a1), "r"(a2), "r"(a3), "r"(b0), "r"(b1));
}

__device__ __forceinline__ void cp16(void* dst_smem, const void* src) {
    uint32_t s = (uint32_t)__cvta_generic_to_shared(dst_smem);
    asm volatile("cp.async.ca.shared.global [%0], [%1], 16;" :: "r"(s), "l"(src));
}
#define CP_COMMIT() asm volatile("cp.async.commit_group;")
#define CP_WAIT0()  asm volatile("cp.async.wait_group 0;")
#define CP_WAIT1()  asm volatile("cp.async.wait_group 1;")

// FFMA-only exp (avoids MUFU bottleneck). Valid for x <= 0 (clamped at -87).
__device__ __forceinline__ float fexp(float x) {
    x = fmaxf(x, -87.0f);
    float t = fmaf(x, 1.4426950408889634f, 12582912.f);
    int   ib = __float_as_int(t);
    float i  = t - 12582912.f;
    float f  = fmaf(x, 1.4426950408889634f, -i);
    float p  = fmaf(f, 0.00133336f, 0.0096181f);
    p = fmaf(f, p, 0.0555041f);
    p = fmaf(f, p, 0.2402265f);
    p = fmaf(f, p, 0.6931472f);
    p = fmaf(f, p, 1.0f);
    float sc = __int_as_float((ib << 23) + 0x3F800000);
    return sc * p;
}

// ---------------------------------------------------------------------------
// one-shot prep kernels
// ---------------------------------------------------------------------------
__global__ void cvt_tf32(const float* __restrict__ in, float* __restrict__ out, int n4) {
    int i = blockIdx.x * 256 + threadIdx.x;
    if (i >= n4) return;
    float4 v = ((const float4*)in)[i];
    v.x = to_tf32(v.x); v.y = to_tf32(v.y); v.z = to_tf32(v.z); v.w = to_tf32(v.w);
    ((float4*)out)[i] = v;
}

__global__ void build_w(const float* __restrict__ u, const float* __restrict__ v,
                        float* __restrict__ w)
{
    int idx = blockIdx.x * 256 + threadIdx.x;
    if (idx >= Hdim * 128 * 256) return;
    int r = idx & 255;
    int n = (idx >> 8) & 127;
    int h = idx >> 15;
    float val = (n < 64)
        ? u[((size_t)h * Rdim + r) * Sdim + n]
        : v[((size_t)h * Rdim + r) * Sdim + (n - 64)];
    w[idx] = to_tf32(val);
}

// ---------------------------------------------------------------------------
// mma.sync tf32 NT GEMM: C[M,N] = A[M,K] * B[N,K]^T (+bias)
// CTA 128x128, BK=32, 8 warps (2x4). Inputs pre-rounded tf32. cp.async 2-stage.
// LAYOUT 0: row-major  LAYOUT 1: V remap [B,H,T,D]  LAYOUT 2: q/k split per head
// ---------------------------------------------------------------------------
#define LDS_PAD 36
template <int LAYOUT, bool HAS_BIAS, bool ROUND>
__global__ void __launch_bounds__(256, 2)
gemm_mma(const float* __restrict__ A, const float* __restrict__ Bw,
         const float* __restrict__ bias, float* __restrict__ C,
         float* __restrict__ C2, int Ndim_, int Kdim_)
{
    extern __shared__ float smem[];
    float* As = smem;                       // [2][128][36]
    float* Bs = smem + 2 * 128 * LDS_PAD;   // [2][128][36]

    const int tid = threadIdx.x;
    const int lane = tid & 31;
    const int warp = tid >> 5;
    const int wy = warp & 1;
    const int wx = warp >> 1;

    const int bm = blockIdx.y * 128;
    const int bn = blockIdx.x * 128;
    if (LAYOUT == 2) Bw += (size_t)blockIdx.z * (128 * 256);

    const int sr = tid >> 3;
    const int sc = (tid & 7) * 4;

    const float* Abase = A + (size_t)bm * Kdim_;
    const float* Bbase = Bw + (size_t)bn * Kdim_;

    float acc[4][4][4];
#pragma unroll
    for (int i = 0; i < 4; i++)
#pragma unroll
        for (int j = 0; j < 4; j++)
#pragma unroll
            for (int e = 0; e < 4; e++) acc[i][j][e] = 0.f;

    const int nch = Kdim_ >> 5;

    auto load_chunk = [&](int ch, int buf) {
        const float* An = Abase + ch * 32;
        const float* Bn = Bbase + ch * 32;
        float* Ad = As + buf * 128 * LDS_PAD;
        float* Bd = Bs + buf * 128 * LDS_PAD;
#pragma unroll
        for (int i = 0; i < 4; i++) {
            int r = sr + i * 32;
            cp16(Ad + r * LDS_PAD + sc, An + (size_t)r * Kdim_ + sc);
            cp16(Bd + r * LDS_PAD + sc, Bn + (size_t)r * Kdim_ + sc);
        }
        CP_COMMIT();
    };

    load_chunk(0, 0);
    if (nch > 1) load_chunk(1, 1);

    const int g = lane >> 2;
    const int tg = lane & 3;

    for (int ch = 0; ch < nch; ch++) {
        if (ch + 1 < nch) { CP_WAIT1(); } else { CP_WAIT0(); }
        __syncthreads();

        const int buf = ch & 1;
        const float* Ab = As + buf * 128 * LDS_PAD + (wy * 64) * LDS_PAD;
        const float* Bb = Bs + buf * 128 * LDS_PAD + (wx * 32) * LDS_PAD;
#pragma unroll
        for (int ks = 0; ks < 4; ks++) {
            const int k0 = ks * 8;
            uint32_t af[4][4];
#pragma unroll
            for (int mf = 0; mf < 4; mf++) {
                const float* ap = Ab + (mf * 16 + g) * LDS_PAD + k0 + tg;
                af[mf][0] = __float_as_uint(ap[0]);
                af[mf][1] = __float_as_uint(ap[8 * LDS_PAD]);
                af[mf][2] = __float_as_uint(ap[4]);
                af[mf][3] = __float_as_uint(ap[8 * LDS_PAD + 4]);
            }
            uint32_t bf[4][2];
#pragma unroll
            for (int nf = 0; nf < 4; nf++) {
                const float* bp = Bb + (nf * 8 + g) * LDS_PAD + k0 + tg;
                bf[nf][0] = __float_as_uint(bp[0]);
                bf[nf][1] = __float_as_uint(bp[4]);
            }
#pragma unroll
            for (int mf = 0; mf < 4; mf++)
#pragma unroll
                for (int nf = 0; nf < 4; nf++)
                    mma_tf32(acc[mf][nf][0], acc[mf][nf][1], acc[mf][nf][2], acc[mf][nf][3],
                             af[mf][0], af[mf][1], af[mf][2], af[mf][3],
                             bf[nf][0], bf[nf][1]);
        }
        __syncthreads();
        if (ch + 2 < nch) load_chunk(ch + 2, buf);
    }

    // epilogue
#pragma unroll
    for (int mf = 0; mf < 4; mf++) {
#pragma unroll
        for (int nf = 0; nf < 4; nf++) {
            const int m0 = bm + wy * 64 + mf * 16 + g;
            const int n0 = bn + wx * 32 + nf * 8 + tg * 2;
            float v0 = acc[mf][nf][0], v1 = acc[mf][nf][1];
            float v2 = acc[mf][nf][2], v3 = acc[mf][nf][3];
            if (HAS_BIAS) {
                float b0 = bias[n0], b1 = bias[n0 + 1];
                v0 += b0; v1 += b1; v2 += b0; v3 += b1;
            }
            if (LAYOUT == 2 && n0 < 64) {
                v0 *= ATTN_SCALE; v1 *= ATTN_SCALE; v2 *= ATTN_SCALE; v3 *= ATTN_SCALE;
            }
            if (ROUND) {
                v0 = to_tf32(v0); v1 = to_tf32(v1); v2 = to_tf32(v2); v3 = to_tf32(v3);
            }
            float2 lo = make_float2(v0, v1);
            float2 hi = make_float2(v2, v3);

            if (LAYOUT == 0) {
                *(float2*)(C + (size_t)m0 * Ndim_ + n0) = lo;
                *(float2*)(C + (size_t)(m0 + 8) * Ndim_ + n0) = hi;
            } else if (LAYOUT == 1) {
                const int h = n0 >> 6, d = n0 & 63;
                const int b_ = m0 >> 11, t = m0 & 2047;
                float* dst = C + (((size_t)b_ * Hdim + h) * Tdim + t) * Ddim + d;
                *(float2*)dst = lo;
                *(float2*)(dst + 8 * Ddim) = hi;
            } else {
                const int h = blockIdx.z;
                float* base = (n0 < 64) ? C : C2;
                const int s0 = n0 & 63;
                const int b_ = m0 >> 11, t = m0 & 2047;
                float* dst = base + (((size_t)b_ * Hdim + h) * Tdim + t) * Sdim + s0;
                *(float2*)dst = lo;
                *(float2*)(dst + 8 * Sdim) = hi;
            }
        }
    }
}

// ---------------------------------------------------------------------------
// Flash attention on mma.sync tf32, cp.async double-buffered K/V.
// Q tile 128 x 64, K/V tiles 64. 8 warps, warp owns 16 Q rows.
// V kept in NATURAL layout (B-fragment reads are conflict-free: bank = 4*tg+g).
// P stays in registers; C-frag -> A-frag relayout via quad shuffles.
// ---------------------------------------------------------------------------
#define FPAD 68
__global__ void __launch_bounds__(256, 2)
flash_mma(const float* __restrict__ q, const float* __restrict__ k,
          const float* __restrict__ v, float* __restrict__ y)
{
    extern __shared__ float sm[];
    float* Qs = sm;                    // [128][68]
    float* Ks = Qs + 128 * FPAD;       // [2][64][68]  natural [u][s]
    float* Vs = Ks + 2 * 64 * FPAD;    // [2][64][68]  natural [u][d]

    const int bh = blockIdx.y;
    const int b = bh >> 4, h = bh & 15;
    const int qb = (gridDim.x - 1) - blockIdx.x;   // heaviest tiles first
    const int q0 = qb * 128;
    const float* Q = q + (size_t)bh * Tdim * Sdim;
    const float* K = k + (size_t)bh * Tdim * Sdim;
    const float* V = v + (size_t)bh * Tdim * Ddim;

    const int tid = threadIdx.x;
    const int lane = tid & 31;
    const int warp = tid >> 5;
    const int wrow = warp * 16;
    const int g = lane >> 2;
    const int tg = lane & 3;

    const int nkt = (q0 + 128) >> 6;

    auto load_kv = [&](int kt, int st) {
        const int k0 = kt * 64;
        float* Kd = Ks + st * 64 * FPAD;
        float* Vd = Vs + st * 64 * FPAD;
#pragma unroll
        for (int i = 0; i < 4; i++) {
            int f = tid + i * 256;
            int u = f >> 4, c4 = f & 15;
            cp16(Kd + u * FPAD + c4 * 4, K + (size_t)(k0 + u) * Sdim + c4 * 4);
            cp16(Vd + u * FPAD + c4 * 4, V + (size_t)(k0 + u) * Ddim + c4 * 4);
        }
        CP_COMMIT();
    };

    load_kv(0, 0);

    // load Q tile (plain vectorized stores)
#pragma unroll
    for (int i = 0; i < 8; i++) {
        int f = tid + i * 256;
        int r = f >> 4, c4 = f & 15;
        *(float4*)&Qs[r * FPAD + c4 * 4] = *(const float4*)&Q[(size_t)(q0 + r) * Sdim + c4 * 4];
    }

    float o[8][4];
#pragma unroll
    for (int df = 0; df < 8; df++)
#pragma unroll
        for (int e = 0; e < 4; e++) o[df][e] = 0.f;
    float m0 = -1e30f, m1 = -1e30f, l0 = 0.f, l1 = 0.f;

    const unsigned FULL = 0xffffffffu;
    const int srcA = (lane & 28) | (tg >> 1);   // g*4 + tg/2
    const int srcB = srcA + 2;

    for (int kt = 0; kt < nkt; kt++) {
        const int st = kt & 1;
        if (kt + 1 < nkt) { load_kv(kt + 1, st ^ 1); CP_WAIT1(); }
        else              { CP_WAIT0(); }
        __syncthreads();

        const float* Kb = Ks + st * 64 * FPAD;
        const float* Vb = Vs + st * 64 * FPAD;
        const int k0 = kt * 64;

        // S = Q K^T  (per warp: 16 x 64)
        float sacc[8][4];
#pragma unroll
        for (int jf = 0; jf < 8; jf++)
#pragma unroll
            for (int e = 0; e < 4; e++) sacc[jf][e] = 0.f;
#pragma unroll
        for (int ks = 0; ks < 8; ks++) {
            const int kk = ks * 8;
            const float* ap = Qs + (wrow + g) * FPAD + kk + tg;
            uint32_t a0 = __float_as_uint(ap[0]);
            uint32_t a1 = __float_as_uint(ap[8 * FPAD]);
            uint32_t a2 = __float_as_uint(ap[4]);
            uint32_t a3 = __float_as_uint(ap[8 * FPAD + 4]);
#pragma unroll
            for (int jf = 0; jf < 8; jf++) {
                const float* bp = Kb + (jf * 8 + g) * FPAD + kk + tg;
                mma_tf32(sacc[jf][0], sacc[jf][1], sacc[jf][2], sacc[jf][3],
                         a0, a1, a2, a3,
                         __float_as_uint(bp[0]), __float_as_uint(bp[4]));
            }
        }

        // causal mask
        const int r0 = q0 + wrow + g;
        const int r1 = r0 + 8;
        if (k0 + 63 > q0 + wrow) {
#pragma unroll
            for (int jf = 0; jf < 8; jf++) {
                const int c0 = k0 + jf * 8 + 2 * tg;
                if (c0 > r0) sacc[jf][0] = -1e30f;
                if (c0 + 1 > r0) sacc[jf][1] = -1e30f;
                if (c0 > r1) sacc[jf][2] = -1e30f;
                if (c0 + 1 > r1) sacc[jf][3] = -1e30f;
            }
        }

        // online softmax (rows r0, r1 shared by the 4 tg lanes)
        float mx0 = -1e30f, mx1 = -1e30f;
#pragma unroll
        for (int jf = 0; jf < 8; jf++) {
            mx0 = fmaxf(mx0, fmaxf(sacc[jf][0], sacc[jf][1]));
            mx1 = fmaxf(mx1, fmaxf(sacc[jf][2], sacc[jf][3]));
        }
        mx0 = fmaxf(mx0, __shfl_xor_sync(FULL, mx0, 1));
        mx0 = fmaxf(mx0, __shfl_xor_sync(FULL, mx0, 2));
        mx1 = fmaxf(mx1, __shfl_xor_sync(FULL, mx1, 1));
        mx1 = fmaxf(mx1, __shfl_xor_sync(FULL, mx1, 2));

        float mn0 = fmaxf(m0, mx0), mn1 = fmaxf(m1, mx1);
        float al0 = fexp(m0 - mn0), al1 = fexp(m1 - mn1);
        m0 = mn0; m1 = mn1;

        float rs0 = 0.f, rs1 = 0.f;
#pragma unroll
        for (int jf = 0; jf < 8; jf++) {
            sacc[jf][0] = fexp(sacc[jf][0] - mn0);
            sacc[jf][1] = fexp(sacc[jf][1] - mn0);
            sacc[jf][2] = fexp(sacc[jf][2] - mn1);
            sacc[jf][3] = fexp(sacc[jf][3] - mn1);
            rs0 += sacc[jf][0] + sacc[jf][1];
            rs1 += sacc[jf][2] + sacc[jf][3];
        }
        rs0 += __shfl_xor_sync(FULL, rs0, 1);
        rs0 += __shfl_xor_sync(FULL, rs0, 2);
        rs1 += __shfl_xor_sync(FULL, rs1, 1);
        rs1 += __shfl_xor_sync(FULL, rs1, 2);
        l0 = l0 * al0 + rs0;
        l1 = l1 * al1 + rs1;

        // rescale O; round P to tf32 in registers
#pragma unroll
        for (int df = 0; df < 8; df++) {
            o[df][0] *= al0; o[df][1] *= al0;
            o[df][2] *= al1; o[df][3] *= al1;
        }
#pragma unroll
        for (int jf = 0; jf < 8; jf++) {
            sacc[jf][0] = to_tf32(sacc[jf][0]);
            sacc[jf][1] = to_tf32(sacc[jf][1]);
            sacc[jf][2] = to_tf32(sacc[jf][2]);
            sacc[jf][3] = to_tf32(sacc[jf][3]);
        }

        // O += P V : A-fragments of P built via quad shuffles, B read from
        // NATURAL V layout (V[u][d], bank = 4*tg+g -> conflict-free)
#pragma unroll
        for (int jf = 0; jf < 8; jf++) {
            float s0 = sacc[jf][0], s1 = sacc[jf][1], s2 = sacc[jf][2], s3 = sacc[jf][3];
            float xA0 = __shfl_sync(FULL, s0, srcA);
            float xA1 = __shfl_sync(FULL, s1, srcA);
            float xA2 = __shfl_sync(FULL, s2, srcA);
            float xA3 = __shfl_sync(FULL, s3, srcA);
            float xB0 = __shfl_sync(FULL, s0, srcB);
            float xB1 = __shfl_sync(FULL, s1, srcB);
            float xB2 = __shfl_sync(FULL, s2, srcB);
            float xB3 = __shfl_sync(FULL, s3, srcB);
            const bool odd = (tg & 1);
            uint32_t a0 = __float_as_uint(odd ? xA1 : xA0);
            uint32_t a1 = __float_as_uint(odd ? xA3 : xA2);
            uint32_t a2 = __float_as_uint(odd ? xB1 : xB0);
            uint32_t a3 = __float_as_uint(odd ? xB3 : xB2);
            const int kk = jf * 8;
            const float* bbase = Vb + (kk + tg) * FPAD + g;
#pragma unroll
            for (int df = 0; df < 8; df++) {
                const float* bp = bbase + df * 8;
                mma_tf32(o[df][0], o[df][1], o[df][2], o[df][3],
                         a0, a1, a2, a3,
                         __float_as_uint(bp[0]), __float_as_uint(bp[4 * FPAD]));
            }
        }
        __syncthreads();   // all warps done reading Kb/Vb before next cp.async overwrite
    }

    // epilogue: y[b, t, h*64 + d], tf32-rounded (feeds o-proj)
    const float inv0 = 1.f / l0, inv1 = 1.f / l1;
    const int r0 = q0 + wrow + g;
    float* y0 = y + ((size_t)b * Tdim + r0) * Cdim + h * 64;
    float* y1 = y + ((size_t)b * Tdim + r0 + 8) * Cdim + h * 64;
#pragma unroll
    for (int df = 0; df < 8; df++) {
        const int d0 = df * 8 + 2 * tg;
        *(float2*)(y0 + d0) = make_float2(to_tf32(o[df][0] * inv0), to_tf32(o[df][1] * inv0));
        *(float2*)(y1 + d0) = make_float2(to_tf32(o[df][2] * inv1), to_tf32(o[df][3] * inv1));
    }
}

// ---------------------------------------------------------------------------
extern "C" void kernel_launch(void* const* d_in, const int* in_sizes, int n_in,
                              void* d_out, int out_size)
{
    const float* x  = (const float*)d_in[0];
    const float* bw = (const float*)d_in[1];
    const float* uf = (const float*)d_in[2];
    const float* vf = (const float*)d_in[3];
    const float* vw = (const float*)d_in[4];
    const float* vb = (const float*)d_in[5];
    const float* ow = (const float*)d_in[6];
    const float* ob = (const float*)d_in[7];
    float* out = (float*)d_out;

    float *latent, *q, *k, *v, *y, *w, *xt, *bwt, *vwt, *owt;
    cudaGetSymbolAddress((void**)&latent, g_latent);
    cudaGetSymbolAddress((void**)&q, g_q);
    cudaGetSymbolAddress((void**)&k, g_k);
    cudaGetSymbolAddress((void**)&v, g_v);
    cudaGetSymbolAddress((void**)&y, g_y);
    cudaGetSymbolAddress((void**)&w, g_w);
    cudaGetSymbolAddress((void**)&xt, g_xt);
    cudaGetSymbolAddress((void**)&bwt, g_bwt);
    cudaGetSymbolAddress((void**)&vwt, g_vwt);
    cudaGetSymbolAddress((void**)&owt, g_owt);

    const int GSMEM = 2 * 2 * 128 * LDS_PAD * 4;                 // 73728
    const int FSMEM = (128 + 2 * 64 + 2 * 64) * FPAD * 4;        // 104448
    cudaFuncSetAttribute(gemm_mma<0, false, true >, cudaFuncAttributeMaxDynamicSharedMemorySize, GSMEM);
    cudaFuncSetAttribute(gemm_mma<0, true,  false>, cudaFuncAttributeMaxDynamicSharedMemorySize, GSMEM);
    cudaFuncSetAttribute(gemm_mma<1, true,  true >, cudaFuncAttributeMaxDynamicSharedMemorySize, GSMEM);
    cudaFuncSetAttribute(gemm_mma<2, false, true >, cudaFuncAttributeMaxDynamicSharedMemorySize, GSMEM);
    cudaFuncSetAttribute(flash_mma, cudaFuncAttributeMaxDynamicSharedMemorySize, FSMEM);

    // one-shot tf32 pre-rounding
    cvt_tf32<<<(Mrows * Cdim / 4 + 255) / 256, 256>>>(x,  xt,  Mrows * Cdim / 4);
    cvt_tf32<<<(Rdim * Cdim / 4 + 255) / 256, 256>>>(bw, bwt, Rdim * Cdim / 4);
    cvt_tf32<<<(Cdim * Cdim / 4 + 255) / 256, 256>>>(vw, vwt, Cdim * Cdim / 4);
    cvt_tf32<<<(Cdim * Cdim / 4 + 255) / 256, 256>>>(ow, owt, Cdim * Cdim / 4);
    build_w<<<(Hdim * 128 * 256 + 255) / 256, 256>>>(uf, vf, w);

    // latent = x * basis_w^T  [8192,256] (tf32-rounded output)
    gemm_mma<0, false, true><<<dim3(Rdim / 128, Mrows / 128), 256, GSMEM>>>(
        xt, bwt, nullptr, latent, nullptr, Rdim, Cdim);

    // q,k per head (q pre-scaled; both tf32-rounded)
    gemm_mma<2, false, true><<<dim3(1, Mrows / 128, Hdim), 256, GSMEM>>>(
        latent, w, nullptr, q, k, 128, Rdim);

    // v = x * v_proj_w^T + b -> [B,H,T,D] (tf32-rounded)
    gemm_mma<1, true, true><<<dim3(Cdim / 128, Mrows / 128), 256, GSMEM>>>(
        xt, vwt, vb, v, nullptr, Cdim, Cdim);

    // causal flash attention (tensor cores) -> y [B,T,C] tf32-rounded
    flash_mma<<<dim3(Tdim / 128, Bdim * Hdim), 256, FSMEM>>>(q, k, v, y);

    // out = y * o_proj_w^T + b (full fp32 output)
    gemm_mma<0, true, false><<<dim3(Cdim / 128, Mrows / 128), 256, GSMEM>>>(
        y, owt, ob, out, nullptr, Cdim, Cdim);
}

// round 6
// speedup vs baseline: 4.6341x; 1.2771x over previous
#include <cuda_runtime.h>
#include <cuda_fp16.h>
#include <cstdint>

// ---------------------------------------------------------------------------
// Problem dims
// ---------------------------------------------------------------------------
#define Bdim 4
#define Tdim 2048
#define Cdim 1024
#define Hdim 16
#define Rdim 256
#define Sdim 64
#define Ddim 64
#define Mrows (Bdim * Tdim)   // 8192
#define ATTN_SCALE 0.125f     // 1/sqrt(64)

// Scratch (device globals; no allocation allowed)
__device__ __align__(16) float  g_q[Bdim * Hdim * Tdim * Sdim];
__device__ __align__(16) float  g_k[Bdim * Hdim * Tdim * Sdim];
__device__ __align__(16) float  g_v[Bdim * Hdim * Tdim * Ddim];
__device__ __align__(16) __half g_xh[Mrows * Cdim];        // x -> fp16
__device__ __align__(16) __half g_bwh[Rdim * Cdim];        // basis_w fp16
__device__ __align__(16) __half g_vwh[Cdim * Cdim];        // v_proj_w fp16
__device__ __align__(16) __half g_owh[Cdim * Cdim];        // o_proj_w fp16
__device__ __align__(16) __half g_wh[Hdim * 128 * 256];    // [H][128][256]=[Uh^T;Vh^T] fp16
__device__ __align__(16) __half g_lath[Mrows * Rdim];      // latent fp16
__device__ __align__(16) __half g_yh[Mrows * Cdim];        // attention output fp16

// ---------------------------------------------------------------------------
// helpers
// ---------------------------------------------------------------------------
__device__ __forceinline__ float to_tf32(float x) {
    uint32_t r;
    asm("cvt.rna.tf32.f32 %0, %1;" : "=r"(r) : "f"(x));
    return __uint_as_float(r);
}

__device__ __forceinline__ void mma_tf32(float& d0, float& d1, float& d2, float& d3,
                                         uint32_t a0, uint32_t a1, uint32_t a2, uint32_t a3,
                                         uint32_t b0, uint32_t b1)
{
    asm volatile(
        "mma.sync.aligned.m16n8k8.row.col.f32.tf32.tf32.f32 "
        "{%0,%1,%2,%3}, {%4,%5,%6,%7}, {%8,%9}, {%0,%1,%2,%3};"
        : "+f"(d0), "+f"(d1), "+f"(d2), "+f"(d3)
        : "r"(a0), "r"(a1), "r"(a2), "r"(a3), "r"(b0), "r"(b1));
}

__device__ __forceinline__ void mma_f16(float& d0, float& d1, float& d2, float& d3,
                                        uint32_t a0, uint32_t a1, uint32_t a2, uint32_t a3,
                                        uint32_t b0, uint32_t b1)
{
    asm volatile(
        "mma.sync.aligned.m16n8k16.row.col.f32.f16.f16.f32 "
        "{%0,%1,%2,%3}, {%4,%5,%6,%7}, {%8,%9}, {%0,%1,%2,%3};"
        : "+f"(d0), "+f"(d1), "+f"(d2), "+f"(d3)
        : "r"(a0), "r"(a1), "r"(a2), "r"(a3), "r"(b0), "r"(b1));
}

__device__ __forceinline__ void cp16(void* dst_smem, const void* src) {
    uint32_t s = (uint32_t)__cvta_generic_to_shared(dst_smem);
    asm volatile("cp.async.ca.shared.global [%0], [%1], 16;" :: "r"(s), "l"(src));
}
#define CP_COMMIT() asm volatile("cp.async.commit_group;")
#define CP_WAIT0()  asm volatile("cp.async.wait_group 0;")
#define CP_WAIT1()  asm volatile("cp.async.wait_group 1;")

// FFMA-only exp (avoids MUFU bottleneck). Valid for x <= 0 (clamped at -87).
__device__ __forceinline__ float fexp(float x) {
    x = fmaxf(x, -87.0f);
    float t = fmaf(x, 1.4426950408889634f, 12582912.f);
    int   ib = __float_as_int(t);
    float i  = t - 12582912.f;
    float f  = fmaf(x, 1.4426950408889634f, -i);
    float p  = fmaf(f, 0.00133336f, 0.0096181f);
    p = fmaf(f, p, 0.0555041f);
    p = fmaf(f, p, 0.2402265f);
    p = fmaf(f, p, 0.6931472f);
    p = fmaf(f, p, 1.0f);
    float sc = __int_as_float((ib << 23) + 0x3F800000);
    return sc * p;
}

// ---------------------------------------------------------------------------
// one-shot prep kernels
// ---------------------------------------------------------------------------
__global__ void cvt_f16(const float* __restrict__ in, __half* __restrict__ out, int n4) {
    int i = blockIdx.x * 256 + threadIdx.x;
    if (i >= n4) return;
    float4 v = ((const float4*)in)[i];
    ((__half2*)out)[2 * i]     = __floats2half2_rn(v.x, v.y);
    ((__half2*)out)[2 * i + 1] = __floats2half2_rn(v.z, v.w);
}

__global__ void build_w(const float* __restrict__ u, const float* __restrict__ v,
                        __half* __restrict__ w)
{
    int idx = blockIdx.x * 256 + threadIdx.x;
    if (idx >= Hdim * 128 * 256) return;
    int r = idx & 255;
    int n = (idx >> 8) & 127;
    int h = idx >> 15;
    float val = (n < 64)
        ? u[((size_t)h * Rdim + r) * Sdim + n]
        : v[((size_t)h * Rdim + r) * Sdim + (n - 64)];
    w[idx] = __float2half_rn(val);
}

// ---------------------------------------------------------------------------
// fp16 mma.sync NT GEMM: C[M,N] = A[M,K] * B[N,K]^T (+bias), fp32 accum.
// CTA 128x128, BK=64 halfs, 8 warps (2x4), warp tile 64x32, cp.async 2-stage.
// LAYOUT 0: row-major  LAYOUT 1: V remap [B,H,T,D]  LAYOUT 2: q/k split per head
// OUT 0: float raw     OUT 1: float tf32-rounded    OUT 2: half
// ---------------------------------------------------------------------------
#define HP 72   // smem pitch in halfs
template <int LAYOUT, bool HAS_BIAS, int OUT>
__global__ void __launch_bounds__(256, 2)
gemm_h(const __half* __restrict__ A, const __half* __restrict__ Bw,
       const float* __restrict__ bias, void* __restrict__ Cv,
       void* __restrict__ C2v, int Ndim_, int Kdim_)
{
    extern __shared__ __half smh[];
    __half* As = smh;                   // [2][128][72]
    __half* Bs = smh + 2 * 128 * HP;    // [2][128][72]

    const int tid = threadIdx.x;
    const int lane = tid & 31;
    const int warp = tid >> 5;
    const int wy = warp & 1;
    const int wx = warp >> 1;

    const int bm = blockIdx.y * 128;
    const int bn = blockIdx.x * 128;
    if (LAYOUT == 2) Bw += (size_t)blockIdx.z * (128 * 256);

    const int sr = tid >> 3;          // 0..31 (x4 rows)
    const int sc8 = (tid & 7) * 8;    // half offset (8 halfs = 16B)

    const __half* Abase = A + (size_t)bm * Kdim_;
    const __half* Bbase = Bw + (size_t)bn * Kdim_;

    float acc[4][4][4];
#pragma unroll
    for (int i = 0; i < 4; i++)
#pragma unroll
        for (int j = 0; j < 4; j++)
#pragma unroll
            for (int e = 0; e < 4; e++) acc[i][j][e] = 0.f;

    const int nch = Kdim_ >> 6;       // K / 64

    auto load_chunk = [&](int ch, int buf) {
        const __half* An = Abase + ch * 64;
        const __half* Bn = Bbase + ch * 64;
        __half* Ad = As + buf * 128 * HP;
        __half* Bd = Bs + buf * 128 * HP;
#pragma unroll
        for (int i = 0; i < 4; i++) {
            int r = sr + i * 32;
            cp16(Ad + r * HP + sc8, An + (size_t)r * Kdim_ + sc8);
            cp16(Bd + r * HP + sc8, Bn + (size_t)r * Kdim_ + sc8);
        }
        CP_COMMIT();
    };

    load_chunk(0, 0);
    if (nch > 1) load_chunk(1, 1);

    const int g = lane >> 2;
    const int tg = lane & 3;

    for (int ch = 0; ch < nch; ch++) {
        if (ch + 1 < nch) { CP_WAIT1(); } else { CP_WAIT0(); }
        __syncthreads();

        const int buf = ch & 1;
        const __half* Ab = As + buf * 128 * HP + (wy * 64) * HP;
        const __half* Bb = Bs + buf * 128 * HP + (wx * 32) * HP;
#pragma unroll
        for (int ks = 0; ks < 4; ks++) {          // 4 k-steps of 16
            const int kk = ks * 16;
            uint32_t af[4][4];
#pragma unroll
            for (int mf = 0; mf < 4; mf++) {
                const __half* ap = Ab + (mf * 16 + g) * HP + kk + 2 * tg;
                af[mf][0] = *(const uint32_t*)(ap);
                af[mf][1] = *(const uint32_t*)(ap + 8 * HP);
                af[mf][2] = *(const uint32_t*)(ap + 8);
                af[mf][3] = *(const uint32_t*)(ap + 8 * HP + 8);
            }
            uint32_t bf[4][2];
#pragma unroll
            for (int nf = 0; nf < 4; nf++) {
                const __half* bp = Bb + (nf * 8 + g) * HP + kk + 2 * tg;
                bf[nf][0] = *(const uint32_t*)(bp);
                bf[nf][1] = *(const uint32_t*)(bp + 8);
            }
#pragma unroll
            for (int mf = 0; mf < 4; mf++)
#pragma unroll
                for (int nf = 0; nf < 4; nf++)
                    mma_f16(acc[mf][nf][0], acc[mf][nf][1], acc[mf][nf][2], acc[mf][nf][3],
                            af[mf][0], af[mf][1], af[mf][2], af[mf][3],
                            bf[nf][0], bf[nf][1]);
        }
        __syncthreads();
        if (ch + 2 < nch) load_chunk(ch + 2, buf);
    }

    // epilogue (C fragment layout identical to tf32 m16n8k8 path)
#pragma unroll
    for (int mf = 0; mf < 4; mf++) {
#pragma unroll
        for (int nf = 0; nf < 4; nf++) {
            const int m0 = bm + wy * 64 + mf * 16 + g;
            const int n0 = bn + wx * 32 + nf * 8 + tg * 2;
            float v0 = acc[mf][nf][0], v1 = acc[mf][nf][1];
            float v2 = acc[mf][nf][2], v3 = acc[mf][nf][3];
            if (HAS_BIAS) {
                float b0 = bias[n0], b1 = bias[n0 + 1];
                v0 += b0; v1 += b1; v2 += b0; v3 += b1;
            }
            if (LAYOUT == 2 && n0 < 64) {
                v0 *= ATTN_SCALE; v1 *= ATTN_SCALE; v2 *= ATTN_SCALE; v3 *= ATTN_SCALE;
            }
            if (OUT == 1) {
                v0 = to_tf32(v0); v1 = to_tf32(v1); v2 = to_tf32(v2); v3 = to_tf32(v3);
            }

            if (OUT == 2) {   // half output (row-major only; used for latent)
                __half* C = (__half*)Cv;
                *(__half2*)(C + (size_t)m0 * Ndim_ + n0) = __floats2half2_rn(v0, v1);
                *(__half2*)(C + (size_t)(m0 + 8) * Ndim_ + n0) = __floats2half2_rn(v2, v3);
            } else {
                float* C = (float*)Cv;
                float* C2 = (float*)C2v;
                float2 lo = make_float2(v0, v1);
                float2 hi = make_float2(v2, v3);
                if (LAYOUT == 0) {
                    *(float2*)(C + (size_t)m0 * Ndim_ + n0) = lo;
                    *(float2*)(C + (size_t)(m0 + 8) * Ndim_ + n0) = hi;
                } else if (LAYOUT == 1) {
                    const int h = n0 >> 6, d = n0 & 63;
                    const int b_ = m0 >> 11, t = m0 & 2047;
                    float* dst = C + (((size_t)b_ * Hdim + h) * Tdim + t) * Ddim + d;
                    *(float2*)dst = lo;
                    *(float2*)(dst + 8 * Ddim) = hi;
                } else {
                    const int h = blockIdx.z;
                    float* base = (n0 < 64) ? C : C2;
                    const int s0 = n0 & 63;
                    const int b_ = m0 >> 11, t = m0 & 2047;
                    float* dst = base + (((size_t)b_ * Hdim + h) * Tdim + t) * Sdim + s0;
                    *(float2*)dst = lo;
                    *(float2*)(dst + 8 * Sdim) = hi;
                }
            }
        }
    }
}

// ---------------------------------------------------------------------------
// Flash attention on mma.sync tf32, cp.async double-buffered K/V (unchanged
// math from round 5); epilogue now emits fp16 y for the fp16 o-projection.
// ---------------------------------------------------------------------------
#define FPAD 68
__global__ void __launch_bounds__(256, 2)
flash_mma(const float* __restrict__ q, const float* __restrict__ k,
          const float* __restrict__ v, __half* __restrict__ y)
{
    extern __shared__ float sm[];
    float* Qs = sm;                    // [128][68]
    float* Ks = Qs + 128 * FPAD;       // [2][64][68]
    float* Vs = Ks + 2 * 64 * FPAD;    // [2][64][68]

    const int bh = blockIdx.y;
    const int b = bh >> 4, h = bh & 15;
    const int qb = (gridDim.x - 1) - blockIdx.x;   // heaviest tiles first
    const int q0 = qb * 128;
    const float* Q = q + (size_t)bh * Tdim * Sdim;
    const float* K = k + (size_t)bh * Tdim * Sdim;
    const float* V = v + (size_t)bh * Tdim * Ddim;

    const int tid = threadIdx.x;
    const int lane = tid & 31;
    const int warp = tid >> 5;
    const int wrow = warp * 16;
    const int g = lane >> 2;
    const int tg = lane & 3;

    const int nkt = (q0 + 128) >> 6;

    auto load_kv = [&](int kt, int st) {
        const int k0 = kt * 64;
        float* Kd = Ks + st * 64 * FPAD;
        float* Vd = Vs + st * 64 * FPAD;
#pragma unroll
        for (int i = 0; i < 4; i++) {
            int f = tid + i * 256;
            int u = f >> 4, c4 = f & 15;
            cp16(Kd + u * FPAD + c4 * 4, K + (size_t)(k0 + u) * Sdim + c4 * 4);
            cp16(Vd + u * FPAD + c4 * 4, V + (size_t)(k0 + u) * Ddim + c4 * 4);
        }
        CP_COMMIT();
    };

    load_kv(0, 0);

#pragma unroll
    for (int i = 0; i < 8; i++) {
        int f = tid + i * 256;
        int r = f >> 4, c4 = f & 15;
        *(float4*)&Qs[r * FPAD + c4 * 4] = *(const float4*)&Q[(size_t)(q0 + r) * Sdim + c4 * 4];
    }

    float o[8][4];
#pragma unroll
    for (int df = 0; df < 8; df++)
#pragma unroll
        for (int e = 0; e < 4; e++) o[df][e] = 0.f;
    float m0 = -1e30f, m1 = -1e30f, l0 = 0.f, l1 = 0.f;

    const unsigned FULL = 0xffffffffu;
    const int srcA = (lane & 28) | (tg >> 1);
    const int srcB = srcA + 2;

    for (int kt = 0; kt < nkt; kt++) {
        const int st = kt & 1;
        if (kt + 1 < nkt) { load_kv(kt + 1, st ^ 1); CP_WAIT1(); }
        else              { CP_WAIT0(); }
        __syncthreads();

        const float* Kb = Ks + st * 64 * FPAD;
        const float* Vb = Vs + st * 64 * FPAD;
        const int k0 = kt * 64;

        float sacc[8][4];
#pragma unroll
        for (int jf = 0; jf < 8; jf++)
#pragma unroll
            for (int e = 0; e < 4; e++) sacc[jf][e] = 0.f;
#pragma unroll
        for (int ks = 0; ks < 8; ks++) {
            const int kk = ks * 8;
            const float* ap = Qs + (wrow + g) * FPAD + kk + tg;
            uint32_t a0 = __float_as_uint(ap[0]);
            uint32_t a1 = __float_as_uint(ap[8 * FPAD]);
            uint32_t a2 = __float_as_uint(ap[4]);
            uint32_t a3 = __float_as_uint(ap[8 * FPAD + 4]);
#pragma unroll
            for (int jf = 0; jf < 8; jf++) {
                const float* bp = Kb + (jf * 8 + g) * FPAD + kk + tg;
                mma_tf32(sacc[jf][0], sacc[jf][1], sacc[jf][2], sacc[jf][3],
                         a0, a1, a2, a3,
                         __float_as_uint(bp[0]), __float_as_uint(bp[4]));
            }
        }

        const int r0 = q0 + wrow + g;
        const int r1 = r0 + 8;
        if (k0 + 63 > q0 + wrow) {
#pragma unroll
            for (int jf = 0; jf < 8; jf++) {
                const int c0 = k0 + jf * 8 + 2 * tg;
                if (c0 > r0) sacc[jf][0] = -1e30f;
                if (c0 + 1 > r0) sacc[jf][1] = -1e30f;
                if (c0 > r1) sacc[jf][2] = -1e30f;
                if (c0 + 1 > r1) sacc[jf][3] = -1e30f;
            }
        }

        float mx0 = -1e30f, mx1 = -1e30f;
#pragma unroll
        for (int jf = 0; jf < 8; jf++) {
            mx0 = fmaxf(mx0, fmaxf(sacc[jf][0], sacc[jf][1]));
            mx1 = fmaxf(mx1, fmaxf(sacc[jf][2], sacc[jf][3]));
        }
        mx0 = fmaxf(mx0, __shfl_xor_sync(FULL, mx0, 1));
        mx0 = fmaxf(mx0, __shfl_xor_sync(FULL, mx0, 2));
        mx1 = fmaxf(mx1, __shfl_xor_sync(FULL, mx1, 1));
        mx1 = fmaxf(mx1, __shfl_xor_sync(FULL, mx1, 2));

        float mn0 = fmaxf(m0, mx0), mn1 = fmaxf(m1, mx1);
        float al0 = fexp(m0 - mn0), al1 = fexp(m1 - mn1);
        m0 = mn0; m1 = mn1;

        float rs0 = 0.f, rs1 = 0.f;
#pragma unroll
        for (int jf = 0; jf < 8; jf++) {
            sacc[jf][0] = fexp(sacc[jf][0] - mn0);
            sacc[jf][1] = fexp(sacc[jf][1] - mn0);
            sacc[jf][2] = fexp(sacc[jf][2] - mn1);
            sacc[jf][3] = fexp(sacc[jf][3] - mn1);
            rs0 += sacc[jf][0] + sacc[jf][1];
            rs1 += sacc[jf][2] + sacc[jf][3];
        }
        rs0 += __shfl_xor_sync(FULL, rs0, 1);
        rs0 += __shfl_xor_sync(FULL, rs0, 2);
        rs1 += __shfl_xor_sync(FULL, rs1, 1);
        rs1 += __shfl_xor_sync(FULL, rs1, 2);
        l0 = l0 * al0 + rs0;
        l1 = l1 * al1 + rs1;

#pragma unroll
        for (int df = 0; df < 8; df++) {
            o[df][0] *= al0; o[df][1] *= al0;
            o[df][2] *= al1; o[df][3] *= al1;
        }
#pragma unroll
        for (int jf = 0; jf < 8; jf++) {
            sacc[jf][0] = to_tf32(sacc[jf][0]);
            sacc[jf][1] = to_tf32(sacc[jf][1]);
            sacc[jf][2] = to_tf32(sacc[jf][2]);
            sacc[jf][3] = to_tf32(sacc[jf][3]);
        }

#pragma unroll
        for (int jf = 0; jf < 8; jf++) {
            float s0 = sacc[jf][0], s1 = sacc[jf][1], s2 = sacc[jf][2], s3 = sacc[jf][3];
            float xA0 = __shfl_sync(FULL, s0, srcA);
            float xA1 = __shfl_sync(FULL, s1, srcA);
            float xA2 = __shfl_sync(FULL, s2, srcA);
            float xA3 = __shfl_sync(FULL, s3, srcA);
            float xB0 = __shfl_sync(FULL, s0, srcB);
            float xB1 = __shfl_sync(FULL, s1, srcB);
            float xB2 = __shfl_sync(FULL, s2, srcB);
            float xB3 = __shfl_sync(FULL, s3, srcB);
            const bool odd = (tg & 1);
            uint32_t a0 = __float_as_uint(odd ? xA1 : xA0);
            uint32_t a1 = __float_as_uint(odd ? xA3 : xA2);
            uint32_t a2 = __float_as_uint(odd ? xB1 : xB0);
            uint32_t a3 = __float_as_uint(odd ? xB3 : xB2);
            const int kk = jf * 8;
            const float* bbase = Vb + (kk + tg) * FPAD + g;
#pragma unroll
            for (int df = 0; df < 8; df++) {
                const float* bp = bbase + df * 8;
                mma_tf32(o[df][0], o[df][1], o[df][2], o[df][3],
                         a0, a1, a2, a3,
                         __float_as_uint(bp[0]), __float_as_uint(bp[4 * FPAD]));
            }
        }
        __syncthreads();
    }

    // epilogue: y[b, t, h*64 + d] as fp16 (feeds fp16 o-proj)
    const float inv0 = 1.f / l0, inv1 = 1.f / l1;
    const int r0 = q0 + wrow + g;
    __half* y0 = y + ((size_t)b * Tdim + r0) * Cdim + h * 64;
    __half* y1 = y + ((size_t)b * Tdim + r0 + 8) * Cdim + h * 64;
#pragma unroll
    for (int df = 0; df < 8; df++) {
        const int d0 = df * 8 + 2 * tg;
        *(__half2*)(y0 + d0) = __floats2half2_rn(o[df][0] * inv0, o[df][1] * inv0);
        *(__half2*)(y1 + d0) = __floats2half2_rn(o[df][2] * inv1, o[df][3] * inv1);
    }
}

// ---------------------------------------------------------------------------
extern "C" void kernel_launch(void* const* d_in, const int* in_sizes, int n_in,
                              void* d_out, int out_size)
{
    const float* x  = (const float*)d_in[0];
    const float* bw = (const float*)d_in[1];
    const float* uf = (const float*)d_in[2];
    const float* vf = (const float*)d_in[3];
    const float* vw = (const float*)d_in[4];
    const float* vb = (const float*)d_in[5];
    const float* ow = (const float*)d_in[6];
    const float* ob = (const float*)d_in[7];
    float* out = (float*)d_out;

    float *q, *k, *v;
    __half *xh, *bwh, *vwh, *owh, *wh, *lath, *yh;
    cudaGetSymbolAddress((void**)&q, g_q);
    cudaGetSymbolAddress((void**)&k, g_k);
    cudaGetSymbolAddress((void**)&v, g_v);
    cudaGetSymbolAddress((void**)&xh, g_xh);
    cudaGetSymbolAddress((void**)&bwh, g_bwh);
    cudaGetSymbolAddress((void**)&vwh, g_vwh);
    cudaGetSymbolAddress((void**)&owh, g_owh);
    cudaGetSymbolAddress((void**)&wh, g_wh);
    cudaGetSymbolAddress((void**)&lath, g_lath);
    cudaGetSymbolAddress((void**)&yh, g_yh);

    const int GSMEM = 2 * 2 * 128 * HP * 2;                  // 73728 bytes
    const int FSMEM = (128 + 2 * 64 + 2 * 64) * FPAD * 4;    // 104448 bytes
    cudaFuncSetAttribute(gemm_h<0, false, 2>, cudaFuncAttributeMaxDynamicSharedMemorySize, GSMEM);
    cudaFuncSetAttribute(gemm_h<2, false, 1>, cudaFuncAttributeMaxDynamicSharedMemorySize, GSMEM);
    cudaFuncSetAttribute(gemm_h<1, true,  1>, cudaFuncAttributeMaxDynamicSharedMemorySize, GSMEM);
    cudaFuncSetAttribute(gemm_h<0, true,  0>, cudaFuncAttributeMaxDynamicSharedMemorySize, GSMEM);
    cudaFuncSetAttribute(flash_mma, cudaFuncAttributeMaxDynamicSharedMemorySize, FSMEM);

    // one-shot fp16 conversion of inputs
    cvt_f16<<<(Mrows * Cdim / 4 + 255) / 256, 256>>>(x,  xh,  Mrows * Cdim / 4);
    cvt_f16<<<(Rdim * Cdim / 4 + 255) / 256, 256>>>(bw, bwh, Rdim * Cdim / 4);
    cvt_f16<<<(Cdim * Cdim / 4 + 255) / 256, 256>>>(vw, vwh, Cdim * Cdim / 4);
    cvt_f16<<<(Cdim * Cdim / 4 + 255) / 256, 256>>>(ow, owh, Cdim * Cdim / 4);
    build_w<<<(Hdim * 128 * 256 + 255) / 256, 256>>>(uf, vf, wh);

    // latent = x * basis_w^T  [8192,256] -> fp16
    gemm_h<0, false, 2><<<dim3(Rdim / 128, Mrows / 128), 256, GSMEM>>>(
        xh, bwh, nullptr, lath, nullptr, Rdim, Cdim);

    // q,k per head (q pre-scaled; float tf32-rounded outputs for flash)
    gemm_h<2, false, 1><<<dim3(1, Mrows / 128, Hdim), 256, GSMEM>>>(
        lath, wh, nullptr, q, k, 128, Rdim);

    // v = x * v_proj_w^T + b -> [B,H,T,D] float tf32-rounded
    gemm_h<1, true, 1><<<dim3(Cdim / 128, Mrows / 128), 256, GSMEM>>>(
        xh, vwh, vb, v, nullptr, Cdim, Cdim);

    // causal flash attention (tf32 tensor cores) -> y fp16
    flash_mma<<<dim3(Tdim / 128, Bdim * Hdim), 256, FSMEM>>>(q, k, v, yh);

    // out = y * o_proj_w^T + b (fp32 output)
    gemm_h<0, true, 0><<<dim3(Cdim / 128, Mrows / 128), 256, GSMEM>>>(
        yh, owh, ob, out, nullptr, Cdim, Cdim);
}

// round 7
// speedup vs baseline: 6.6869x; 1.4430x over previous
#include <cuda_runtime.h>
#include <cuda_fp16.h>
#include <cstdint>

// ---------------------------------------------------------------------------
// Problem dims
// ---------------------------------------------------------------------------
#define Bdim 4
#define Tdim 2048
#define Cdim 1024
#define Hdim 16
#define Rdim 256
#define Sdim 64
#define Ddim 64
#define Mrows (Bdim * Tdim)   // 8192
#define ATTN_SCALE 0.125f     // 1/sqrt(64)

// Scratch (device globals; no allocation allowed)
__device__ __align__(16) __half g_qh[Bdim * Hdim * Tdim * Sdim];
__device__ __align__(16) __half g_kh[Bdim * Hdim * Tdim * Sdim];
__device__ __align__(16) __half g_vh[Bdim * Hdim * Tdim * Ddim];
__device__ __align__(16) __half g_xh[Mrows * Cdim];        // x -> fp16
__device__ __align__(16) __half g_bwh[Rdim * Cdim];        // basis_w fp16
__device__ __align__(16) __half g_vwh[Cdim * Cdim];        // v_proj_w fp16
__device__ __align__(16) __half g_owh[Cdim * Cdim];        // o_proj_w fp16
__device__ __align__(16) __half g_wh[Hdim * 128 * 256];    // [H][128][256]=[Uh^T;Vh^T] fp16
__device__ __align__(16) __half g_lath[Mrows * Rdim];      // latent fp16
__device__ __align__(16) __half g_yh[Mrows * Cdim];        // attention output fp16

// ---------------------------------------------------------------------------
// helpers
// ---------------------------------------------------------------------------
__device__ __forceinline__ void mma_f16(float& d0, float& d1, float& d2, float& d3,
                                        uint32_t a0, uint32_t a1, uint32_t a2, uint32_t a3,
                                        uint32_t b0, uint32_t b1)
{
    asm volatile(
        "mma.sync.aligned.m16n8k16.row.col.f32.f16.f16.f32 "
        "{%0,%1,%2,%3}, {%4,%5,%6,%7}, {%8,%9}, {%0,%1,%2,%3};"
        : "+f"(d0), "+f"(d1), "+f"(d2), "+f"(d3)
        : "r"(a0), "r"(a1), "r"(a2), "r"(a3), "r"(b0), "r"(b1));
}

__device__ __forceinline__ void ldmatrix_x4_trans(
    uint32_t& r0, uint32_t& r1, uint32_t& r2, uint32_t& r3, uint32_t saddr)
{
    asm volatile(
        "ldmatrix.sync.aligned.m8n8.x4.trans.shared.b16 {%0,%1,%2,%3}, [%4];"
        : "=r"(r0), "=r"(r1), "=r"(r2), "=r"(r3)
        : "r"(saddr));
}

__device__ __forceinline__ void cp16(void* dst_smem, const void* src) {
    uint32_t s = (uint32_t)__cvta_generic_to_shared(dst_smem);
    asm volatile("cp.async.ca.shared.global [%0], [%1], 16;" :: "r"(s), "l"(src));
}
#define CP_COMMIT() asm volatile("cp.async.commit_group;")
#define CP_WAIT0()  asm volatile("cp.async.wait_group 0;")
#define CP_WAIT1()  asm volatile("cp.async.wait_group 1;")

// FFMA-only exp (avoids MUFU bottleneck). Valid for x <= 0 (clamped at -87).
__device__ __forceinline__ float fexp(float x) {
    x = fmaxf(x, -87.0f);
    float t = fmaf(x, 1.4426950408889634f, 12582912.f);
    int   ib = __float_as_int(t);
    float i  = t - 12582912.f;
    float f  = fmaf(x, 1.4426950408889634f, -i);
    float p  = fmaf(f, 0.00133336f, 0.0096181f);
    p = fmaf(f, p, 0.0555041f);
    p = fmaf(f, p, 0.2402265f);
    p = fmaf(f, p, 0.6931472f);
    p = fmaf(f, p, 1.0f);
    float sc = __int_as_float((ib << 23) + 0x3F800000);
    return sc * p;
}

__device__ __forceinline__ uint32_t packh2(float a, float b) {
    __half2 h = __floats2half2_rn(a, b);
    return *(uint32_t*)&h;
}

// ---------------------------------------------------------------------------
// one-shot prep kernels
// ---------------------------------------------------------------------------
__global__ void cvt_f16(const float* __restrict__ in, __half* __restrict__ out, int n4) {
    int i = blockIdx.x * 256 + threadIdx.x;
    if (i >= n4) return;
    float4 v = ((const float4*)in)[i];
    ((__half2*)out)[2 * i]     = __floats2half2_rn(v.x, v.y);
    ((__half2*)out)[2 * i + 1] = __floats2half2_rn(v.z, v.w);
}

__global__ void build_w(const float* __restrict__ u, const float* __restrict__ v,
                        __half* __restrict__ w)
{
    int idx = blockIdx.x * 256 + threadIdx.x;
    if (idx >= Hdim * 128 * 256) return;
    int r = idx & 255;
    int n = (idx >> 8) & 127;
    int h = idx >> 15;
    float val = (n < 64)
        ? u[((size_t)h * Rdim + r) * Sdim + n]
        : v[((size_t)h * Rdim + r) * Sdim + (n - 64)];
    w[idx] = __float2half_rn(val);
}

// ---------------------------------------------------------------------------
// fp16 mma.sync NT GEMM: C[M,N] = A[M,K] * B[N,K]^T (+bias), fp32 accum.
// CTA 128x128, BK=64 halfs, 8 warps (2x4), warp tile 64x32, cp.async 2-stage.
// LAYOUT 0: row-major  LAYOUT 1: V remap [B,H,T,D]  LAYOUT 2: q/k split per head
// OUT 0: float raw     OUT 2: half
// ---------------------------------------------------------------------------
#define HP 72   // smem pitch in halfs
template <int LAYOUT, bool HAS_BIAS, int OUT>
__global__ void __launch_bounds__(256, 2)
gemm_h(const __half* __restrict__ A, const __half* __restrict__ Bw,
       const float* __restrict__ bias, void* __restrict__ Cv,
       void* __restrict__ C2v, int Ndim_, int Kdim_)
{
    extern __shared__ __half smh[];
    __half* As = smh;                   // [2][128][72]
    __half* Bs = smh + 2 * 128 * HP;    // [2][128][72]

    const int tid = threadIdx.x;
    const int lane = tid & 31;
    const int warp = tid >> 5;
    const int wy = warp & 1;
    const int wx = warp >> 1;

    const int bm = blockIdx.y * 128;
    const int bn = blockIdx.x * 128;
    if (LAYOUT == 2) Bw += (size_t)blockIdx.z * (128 * 256);

    const int sr = tid >> 3;          // 0..31 (x4 rows)
    const int sc8 = (tid & 7) * 8;    // half offset (8 halfs = 16B)

    const __half* Abase = A + (size_t)bm * Kdim_;
    const __half* Bbase = Bw + (size_t)bn * Kdim_;

    float acc[4][4][4];
#pragma unroll
    for (int i = 0; i < 4; i++)
#pragma unroll
        for (int j = 0; j < 4; j++)
#pragma unroll
            for (int e = 0; e < 4; e++) acc[i][j][e] = 0.f;

    const int nch = Kdim_ >> 6;       // K / 64

    auto load_chunk = [&](int ch, int buf) {
        const __half* An = Abase + ch * 64;
        const __half* Bn = Bbase + ch * 64;
        __half* Ad = As + buf * 128 * HP;
        __half* Bd = Bs + buf * 128 * HP;
#pragma unroll
        for (int i = 0; i < 4; i++) {
            int r = sr + i * 32;
            cp16(Ad + r * HP + sc8, An + (size_t)r * Kdim_ + sc8);
            cp16(Bd + r * HP + sc8, Bn + (size_t)r * Kdim_ + sc8);
        }
        CP_COMMIT();
    };

    load_chunk(0, 0);
    if (nch > 1) load_chunk(1, 1);

    const int g = lane >> 2;
    const int tg = lane & 3;

    for (int ch = 0; ch < nch; ch++) {
        if (ch + 1 < nch) { CP_WAIT1(); } else { CP_WAIT0(); }
        __syncthreads();

        const int buf = ch & 1;
        const __half* Ab = As + buf * 128 * HP + (wy * 64) * HP;
        const __half* Bb = Bs + buf * 128 * HP + (wx * 32) * HP;
#pragma unroll
        for (int ks = 0; ks < 4; ks++) {          // 4 k-steps of 16
            const int kk = ks * 16;
            uint32_t af[4][4];
#pragma unroll
            for (int mf = 0; mf < 4; mf++) {
                const __half* ap = Ab + (mf * 16 + g) * HP + kk + 2 * tg;
                af[mf][0] = *(const uint32_t*)(ap);
                af[mf][1] = *(const uint32_t*)(ap + 8 * HP);
                af[mf][2] = *(const uint32_t*)(ap + 8);
                af[mf][3] = *(const uint32_t*)(ap + 8 * HP + 8);
            }
            uint32_t bf[4][2];
#pragma unroll
            for (int nf = 0; nf < 4; nf++) {
                const __half* bp = Bb + (nf * 8 + g) * HP + kk + 2 * tg;
                bf[nf][0] = *(const uint32_t*)(bp);
                bf[nf][1] = *(const uint32_t*)(bp + 8);
            }
#pragma unroll
            for (int mf = 0; mf < 4; mf++)
#pragma unroll
                for (int nf = 0; nf < 4; nf++)
                    mma_f16(acc[mf][nf][0], acc[mf][nf][1], acc[mf][nf][2], acc[mf][nf][3],
                            af[mf][0], af[mf][1], af[mf][2], af[mf][3],
                            bf[nf][0], bf[nf][1]);
        }
        __syncthreads();
        if (ch + 2 < nch) load_chunk(ch + 2, buf);
    }

    // epilogue
#pragma unroll
    for (int mf = 0; mf < 4; mf++) {
#pragma unroll
        for (int nf = 0; nf < 4; nf++) {
            const int m0 = bm + wy * 64 + mf * 16 + g;
            const int n0 = bn + wx * 32 + nf * 8 + tg * 2;
            float v0 = acc[mf][nf][0], v1 = acc[mf][nf][1];
            float v2 = acc[mf][nf][2], v3 = acc[mf][nf][3];
            if (HAS_BIAS) {
                float b0 = bias[n0], b1 = bias[n0 + 1];
                v0 += b0; v1 += b1; v2 += b0; v3 += b1;
            }
            if (LAYOUT == 2 && n0 < 64) {
                v0 *= ATTN_SCALE; v1 *= ATTN_SCALE; v2 *= ATTN_SCALE; v3 *= ATTN_SCALE;
            }

            if (OUT == 2) {   // half outputs
                __half2 lo = __floats2half2_rn(v0, v1);
                __half2 hi = __floats2half2_rn(v2, v3);
                if (LAYOUT == 0) {
                    __half* C = (__half*)Cv;
                    *(__half2*)(C + (size_t)m0 * Ndim_ + n0) = lo;
                    *(__half2*)(C + (size_t)(m0 + 8) * Ndim_ + n0) = hi;
                } else if (LAYOUT == 1) {
                    __half* C = (__half*)Cv;
                    const int h = n0 >> 6, d = n0 & 63;
                    const int b_ = m0 >> 11, t = m0 & 2047;
                    __half* dst = C + (((size_t)b_ * Hdim + h) * Tdim + t) * Ddim + d;
                    *(__half2*)dst = lo;
                    *(__half2*)(dst + 8 * Ddim) = hi;
                } else {
                    const int h = blockIdx.z;
                    __half* base = (n0 < 64) ? (__half*)Cv : (__half*)C2v;
                    const int s0 = n0 & 63;
                    const int b_ = m0 >> 11, t = m0 & 2047;
                    __half* dst = base + (((size_t)b_ * Hdim + h) * Tdim + t) * Sdim + s0;
                    *(__half2*)dst = lo;
                    *(__half2*)(dst + 8 * Sdim) = hi;
                }
            } else {          // float row-major (final output)
                float* C = (float*)Cv;
                *(float2*)(C + (size_t)m0 * Ndim_ + n0) = make_float2(v0, v1);
                *(float2*)(C + (size_t)(m0 + 8) * Ndim_ + n0) = make_float2(v2, v3);
            }
        }
    }
}

// ---------------------------------------------------------------------------
// Flash attention on fp16 mma.sync (m16n8k16), fp32 accum, cp.async 2-stage.
// Q tile 128x64, K/V tiles 64. 8 warps, warp owns 16 Q rows.
// P relayout C-frag -> A-frag is pure packing (no shuffles).
// V kept natural [u][d]; B-fragments via ldmatrix.x4.trans.
// ---------------------------------------------------------------------------
__global__ void __launch_bounds__(256, 2)
flash_h(const __half* __restrict__ q, const __half* __restrict__ k,
        const __half* __restrict__ v, __half* __restrict__ y)
{
    extern __shared__ __half fsh[];
    __half* Qs = fsh;                  // [128][72]
    __half* Ks = Qs + 128 * HP;        // [2][64][72]
    __half* Vs = Ks + 2 * 64 * HP;     // [2][64][72] natural [u][d]

    const int bh = blockIdx.y;
    const int b = bh >> 4, h = bh & 15;
    const int qb = (gridDim.x - 1) - blockIdx.x;   // heaviest tiles first
    const int q0 = qb * 128;
    const __half* Q = q + (size_t)bh * Tdim * Sdim;
    const __half* K = k + (size_t)bh * Tdim * Sdim;
    const __half* V = v + (size_t)bh * Tdim * Ddim;

    const int tid = threadIdx.x;
    const int lane = tid & 31;
    const int warp = tid >> 5;
    const int wrow = warp * 16;
    const int g = lane >> 2;
    const int tg = lane & 3;

    const int nkt = (q0 + 128) >> 6;

    auto load_kv = [&](int kt, int st) {
        const int k0 = kt * 64;
        __half* Kd = Ks + st * 64 * HP;
        __half* Vd = Vs + st * 64 * HP;
#pragma unroll
        for (int i = 0; i < 2; i++) {
            int f = tid + i * 256;
            int u = f >> 3, c8 = (f & 7) * 8;
            cp16(Kd + u * HP + c8, K + (size_t)(k0 + u) * Sdim + c8);
            cp16(Vd + u * HP + c8, V + (size_t)(k0 + u) * Ddim + c8);
        }
        CP_COMMIT();
    };

    load_kv(0, 0);

    // load Q tile: 128 rows x 64 halfs (uint4 = 8 halfs)
#pragma unroll
    for (int i = 0; i < 4; i++) {
        int f = tid + i * 256;
        int r = f >> 3, c8 = (f & 7) * 8;
        *(uint4*)&Qs[r * HP + c8] = *(const uint4*)&Q[(size_t)(q0 + r) * Sdim + c8];
    }

    float o[8][4];
#pragma unroll
    for (int df = 0; df < 8; df++)
#pragma unroll
        for (int e = 0; e < 4; e++) o[df][e] = 0.f;
    float m0 = -1e30f, m1 = -1e30f, l0 = 0.f, l1 = 0.f;

    const unsigned FULL = 0xffffffffu;
    // ldmatrix lane -> (row-within-kblock, df-offset): matrices m0..m3 by lane>>3
    const int lm_row = ((lane >> 3) & 1) * 8 + (lane & 7);  // k row within 16-block
    const int lm_dfo = lane >> 4;                           // 0 or 1 (n 8-block)

    for (int kt = 0; kt < nkt; kt++) {
        const int st = kt & 1;
        if (kt + 1 < nkt) { load_kv(kt + 1, st ^ 1); CP_WAIT1(); }
        else              { CP_WAIT0(); }
        __syncthreads();

        const __half* Kb = Ks + st * 64 * HP;
        const __half* Vb = Vs + st * 64 * HP;
        const int k0 = kt * 64;

        // S = Q K^T  (per warp: 16 x 64), fp16 mma
        float sacc[8][4];
#pragma unroll
        for (int jf = 0; jf < 8; jf++)
#pragma unroll
            for (int e = 0; e < 4; e++) sacc[jf][e] = 0.f;
#pragma unroll
        for (int ks = 0; ks < 4; ks++) {
            const int kk = ks * 16;
            const __half* ap = Qs + (wrow + g) * HP + kk + 2 * tg;
            uint32_t a0 = *(const uint32_t*)(ap);
            uint32_t a1 = *(const uint32_t*)(ap + 8 * HP);
            uint32_t a2 = *(const uint32_t*)(ap + 8);
            uint32_t a3 = *(const uint32_t*)(ap + 8 * HP + 8);
#pragma unroll
            for (int jf = 0; jf < 8; jf++) {
                const __half* bp = Kb + (jf * 8 + g) * HP + kk + 2 * tg;
                mma_f16(sacc[jf][0], sacc[jf][1], sacc[jf][2], sacc[jf][3],
                        a0, a1, a2, a3,
                        *(const uint32_t*)(bp), *(const uint32_t*)(bp + 8));
            }
        }

        // causal mask
        const int r0 = q0 + wrow + g;
        const int r1 = r0 + 8;
        if (k0 + 63 > q0 + wrow) {
#pragma unroll
            for (int jf = 0; jf < 8; jf++) {
                const int c0 = k0 + jf * 8 + 2 * tg;
                if (c0 > r0) sacc[jf][0] = -1e30f;
                if (c0 + 1 > r0) sacc[jf][1] = -1e30f;
                if (c0 > r1) sacc[jf][2] = -1e30f;
                if (c0 + 1 > r1) sacc[jf][3] = -1e30f;
            }
        }

        // online softmax (rows r0, r1; row shared by the 4 tg lanes)
        float mx0 = -1e30f, mx1 = -1e30f;
#pragma unroll
        for (int jf = 0; jf < 8; jf++) {
            mx0 = fmaxf(mx0, fmaxf(sacc[jf][0], sacc[jf][1]));
            mx1 = fmaxf(mx1, fmaxf(sacc[jf][2], sacc[jf][3]));
        }
        mx0 = fmaxf(mx0, __shfl_xor_sync(FULL, mx0, 1));
        mx0 = fmaxf(mx0, __shfl_xor_sync(FULL, mx0, 2));
        mx1 = fmaxf(mx1, __shfl_xor_sync(FULL, mx1, 1));
        mx1 = fmaxf(mx1, __shfl_xor_sync(FULL, mx1, 2));

        float mn0 = fmaxf(m0, mx0), mn1 = fmaxf(m1, mx1);
        float al0 = fexp(m0 - mn0), al1 = fexp(m1 - mn1);
        m0 = mn0; m1 = mn1;

        float rs0 = 0.f, rs1 = 0.f;
#pragma unroll
        for (int jf = 0; jf < 8; jf++) {
            sacc[jf][0] = fexp(sacc[jf][0] - mn0);
            sacc[jf][1] = fexp(sacc[jf][1] - mn0);
            sacc[jf][2] = fexp(sacc[jf][2] - mn1);
            sacc[jf][3] = fexp(sacc[jf][3] - mn1);
            rs0 += sacc[jf][0] + sacc[jf][1];
            rs1 += sacc[jf][2] + sacc[jf][3];
        }
        rs0 += __shfl_xor_sync(FULL, rs0, 1);
        rs0 += __shfl_xor_sync(FULL, rs0, 2);
        rs1 += __shfl_xor_sync(FULL, rs1, 1);
        rs1 += __shfl_xor_sync(FULL, rs1, 2);
        l0 = l0 * al0 + rs0;
        l1 = l1 * al1 + rs1;

        // rescale O
#pragma unroll
        for (int df = 0; df < 8; df++) {
            o[df][0] *= al0; o[df][1] *= al0;
            o[df][2] *= al1; o[df][3] *= al1;
        }

        // O += P V : P A-fragments by packing C-frags (no shuffles);
        // V B-fragments via ldmatrix.x4.trans from natural layout.
        const uint32_t vb_s = (uint32_t)__cvta_generic_to_shared(Vb);
#pragma unroll
        for (int ks2 = 0; ks2 < 4; ks2++) {
            uint32_t a0 = packh2(sacc[2 * ks2][0],     sacc[2 * ks2][1]);
            uint32_t a1 = packh2(sacc[2 * ks2][2],     sacc[2 * ks2][3]);
            uint32_t a2 = packh2(sacc[2 * ks2 + 1][0], sacc[2 * ks2 + 1][1]);
            uint32_t a3 = packh2(sacc[2 * ks2 + 1][2], sacc[2 * ks2 + 1][3]);
            const uint32_t rowaddr = vb_s + ((16 * ks2 + lm_row) * HP) * 2;
#pragma unroll
            for (int df2 = 0; df2 < 4; df2++) {
                uint32_t b0, b1, b2, b3;
                ldmatrix_x4_trans(b0, b1, b2, b3,
                                  rowaddr + (16 * df2 + 8 * lm_dfo) * 2);
                mma_f16(o[2 * df2][0], o[2 * df2][1], o[2 * df2][2], o[2 * df2][3],
                        a0, a1, a2, a3, b0, b1);
                mma_f16(o[2 * df2 + 1][0], o[2 * df2 + 1][1], o[2 * df2 + 1][2], o[2 * df2 + 1][3],
                        a0, a1, a2, a3, b2, b3);
            }
        }
        __syncthreads();   // all warps done reading Kb/Vb before next cp.async
    }

    // epilogue: y[b, t, h*64 + d] as fp16 (feeds fp16 o-proj)
    const float inv0 = 1.f / l0, inv1 = 1.f / l1;
    const int r0 = q0 + wrow + g;
    __half* y0 = y + ((size_t)b * Tdim + r0) * Cdim + h * 64;
    __half* y1 = y + ((size_t)b * Tdim + r0 + 8) * Cdim + h * 64;
#pragma unroll
    for (int df = 0; df < 8; df++) {
        const int d0 = df * 8 + 2 * tg;
        *(__half2*)(y0 + d0) = __floats2half2_rn(o[df][0] * inv0, o[df][1] * inv0);
        *(__half2*)(y1 + d0) = __floats2half2_rn(o[df][2] * inv1, o[df][3] * inv1);
    }
}

// ---------------------------------------------------------------------------
extern "C" void kernel_launch(void* const* d_in, const int* in_sizes, int n_in,
                              void* d_out, int out_size)
{
    const float* x  = (const float*)d_in[0];
    const float* bw = (const float*)d_in[1];
    const float* uf = (const float*)d_in[2];
    const float* vf = (const float*)d_in[3];
    const float* vw = (const float*)d_in[4];
    const float* vb = (const float*)d_in[5];
    const float* ow = (const float*)d_in[6];
    const float* ob = (const float*)d_in[7];
    float* out = (float*)d_out;

    __half *qh, *kh, *vh, *xh, *bwh, *vwh, *owh, *wh, *lath, *yh;
    cudaGetSymbolAddress((void**)&qh, g_qh);
    cudaGetSymbolAddress((void**)&kh, g_kh);
    cudaGetSymbolAddress((void**)&vh, g_vh);
    cudaGetSymbolAddress((void**)&xh, g_xh);
    cudaGetSymbolAddress((void**)&bwh, g_bwh);
    cudaGetSymbolAddress((void**)&vwh, g_vwh);
    cudaGetSymbolAddress((void**)&owh, g_owh);
    cudaGetSymbolAddress((void**)&wh, g_wh);
    cudaGetSymbolAddress((void**)&lath, g_lath);
    cudaGetSymbolAddress((void**)&yh, g_yh);

    const int GSMEM = 2 * 2 * 128 * HP * 2;             // 73728 bytes
    const int FSMEM = (128 + 2 * 64 + 2 * 64) * HP * 2; // 55296 bytes
    cudaFuncSetAttribute(gemm_h<0, false, 2>, cudaFuncAttributeMaxDynamicSharedMemorySize, GSMEM);
    cudaFuncSetAttribute(gemm_h<2, false, 2>, cudaFuncAttributeMaxDynamicSharedMemorySize, GSMEM);
    cudaFuncSetAttribute(gemm_h<1, true,  2>, cudaFuncAttributeMaxDynamicSharedMemorySize, GSMEM);
    cudaFuncSetAttribute(gemm_h<0, true,  0>, cudaFuncAttributeMaxDynamicSharedMemorySize, GSMEM);
    cudaFuncSetAttribute(flash_h, cudaFuncAttributeMaxDynamicSharedMemorySize, FSMEM);

    // one-shot fp16 conversion of inputs
    cvt_f16<<<(Mrows * Cdim / 4 + 255) / 256, 256>>>(x,  xh,  Mrows * Cdim / 4);
    cvt_f16<<<(Rdim * Cdim / 4 + 255) / 256, 256>>>(bw, bwh, Rdim * Cdim / 4);
    cvt_f16<<<(Cdim * Cdim / 4 + 255) / 256, 256>>>(vw, vwh, Cdim * Cdim / 4);
    cvt_f16<<<(Cdim * Cdim / 4 + 255) / 256, 256>>>(ow, owh, Cdim * Cdim / 4);
    build_w<<<(Hdim * 128 * 256 + 255) / 256, 256>>>(uf, vf, wh);

    // latent = x * basis_w^T  [8192,256] -> fp16
    gemm_h<0, false, 2><<<dim3(Rdim / 128, Mrows / 128), 256, GSMEM>>>(
        xh, bwh, nullptr, lath, nullptr, Rdim, Cdim);

    // q,k per head (q pre-scaled) -> fp16 [B,H,T,64]
    gemm_h<2, false, 2><<<dim3(1, Mrows / 128, Hdim), 256, GSMEM>>>(
        lath, wh, nullptr, qh, kh, 128, Rdim);

    // v = x * v_proj_w^T + b -> fp16 [B,H,T,D]
    gemm_h<1, true, 2><<<dim3(Cdim / 128, Mrows / 128), 256, GSMEM>>>(
        xh, vwh, vb, vh, nullptr, Cdim, Cdim);

    // causal flash attention (fp16 tensor cores) -> y fp16
    flash_h<<<dim3(Tdim / 128, Bdim * Hdim), 256, FSMEM>>>(qh, kh, vh, yh);

    // out = y * o_proj_w^T + b (fp32 output)
    gemm_h<0, true, 0><<<dim3(Cdim / 128, Mrows / 128), 256, GSMEM>>>(
        yh, owh, ob, out, nullptr, Cdim, Cdim);
}